// round 15
// baseline (speedup 1.0000x reference)
#include <cuda_runtime.h>
#include <cuda_fp16.h>
#include <mma.h>
#include <math.h>

using namespace nvcuda;

#define BB 1024
#define HH 1024
#define DD 512
#define PP 66
#define TIN 10
#define TOUT 25
#define GG 4096   // 4*HH

// ---------------- static device scratch (no allocations allowed) ----------------
__device__ float d_WcombX[(size_t)GG * 256];
__device__ float d_WcombZ[(size_t)GG * 256];
__device__ float d_bcombX[GG];
__device__ float d_bcombZ[GG];
__device__ float d_WeffF[(size_t)GG * HH];             // dec_wih @ lin_w, f32
__device__ __half d_Wcat16[(size_t)GG * 2048];         // fp16: [dec_whh | Weff]
__device__ __half d_whhX16[(size_t)GG * HH];
__device__ __half d_whhZ16[(size_t)GG * HH];
__device__ __half d_poseW16[128 * HH];                 // pose_w padded to 128 rows, fp16
__device__ float d_bcat[GG];
__device__ float d_ginX[(size_t)TIN * BB * GG];
__device__ float d_ginZ[(size_t)TIN * BB * GG];
__device__ __half d_allh16X[(size_t)TIN * BB * HH];
__device__ __half d_allh16Z[(size_t)TIN * BB * HH];
__device__ float d_cX[BB * HH];
__device__ float d_cZ[BB * HH];
__device__ float d_decc[BB * HH];
__device__ float d_gates[(size_t)2 * BB * GG];
__device__ __half d_hcat16[(size_t)BB * 2048];         // [atth | h_n] fp16
__device__ __half d_dechs16[(size_t)TOUT * BB * HH];   // fp16 (attention + pose input)
__device__ float d_poseC[(size_t)TOUT * BB * 128];     // pose GEMM output (padded 128)

// ================= helpers =================
__device__ __forceinline__ unsigned sptr(const void* p) {
    return (unsigned)__cvta_generic_to_shared(p);
}
__device__ __forceinline__ void cpa16(unsigned d, const void* s, bool pr) {
    int sz = pr ? 16 : 0;
    asm volatile("cp.async.cg.shared.global [%0], [%1], 16, %2;\n" :: "r"(d), "l"(s), "r"(sz));
}
__device__ __forceinline__ void cpa16u(unsigned d, const void* s) {
    asm volatile("cp.async.cg.shared.global [%0], [%1], 16;\n" :: "r"(d), "l"(s));
}
__device__ __forceinline__ void cpa4(unsigned d, const void* s, bool pr) {
    int sz = pr ? 4 : 0;
    asm volatile("cp.async.ca.shared.global [%0], [%1], 4, %2;\n" :: "r"(d), "l"(s), "r"(sz));
}
__device__ __forceinline__ float tanha(float x) {
    float y;
    asm("tanh.approx.f32 %0, %1;" : "=f"(y) : "f"(x));
    return y;
}
__device__ __forceinline__ float sigma(float x) {
    return 0.5f + 0.5f * tanha(0.5f * x);
}
// dot of 8 fp16 (one float4) with 8 f32 (two float4)
__device__ __forceinline__ float dot8(float4 hv, float4 c0, float4 c1) {
    const __half2* h2 = (const __half2*)&hv;
    float2 a0 = __half22float2(h2[0]);
    float2 a1 = __half22float2(h2[1]);
    float2 a2 = __half22float2(h2[2]);
    float2 a3 = __half22float2(h2[3]);
    return a0.x * c0.x + a0.y * c0.y + a1.x * c0.z + a1.y * c0.w
         + a2.x * c1.x + a2.y * c1.y + a3.x * c1.z + a3.y * c1.w;
}

// ================= fp16 recurrent GEMM: 128x128 block, 64x32 warp tile, k-chunk 64 =================
struct GP16 {
    const __half* A;     // [M, K] row-major
    const __half* Bm;    // [N, K] row-major (weights)
    float* C;            // [M, N]
    int M, N, K, lda, ldb, ldc;
};

#define H_LD 72                          // halfs per smem row (64 + 8 pad)
#define H_TILE (128 * H_LD)
#define H_STAGE (2 * H_TILE)
#define H_NSTAGE 3
#define H_SMEM_BYTES (H_NSTAGE * H_STAGE * 2)   // 110592 B

__global__ __launch_bounds__(256, 2) void hgemm16_k(GP16 p0, GP16 p1) {
    extern __shared__ __half smh[];
    GP16 p = (blockIdx.z == 0) ? p0 : p1;
    const int tid = threadIdx.x;
    const int warp = tid >> 5;
    const int wm = warp & 1;             // 2 x 4 warp grid, warp tile 64m x 32n
    const int wn = warp >> 1;
    const int m0 = blockIdx.x * 128, n0 = blockIdx.y * 128;
    const int KT = p.K >> 6;             // 64-k chunks

    wmma::fragment<wmma::accumulator, 16, 16, 16, float> acc[4][2];
#pragma unroll
    for (int i = 0; i < 4; i++)
#pragma unroll
        for (int j = 0; j < 2; j++) wmma::fill_fragment(acc[i][j], 0.f);

    auto loadChunk = [&](int kt, int stg) {
        __half* As = smh + stg * H_STAGE;
        __half* Bs = As + H_TILE;
        const int k0 = kt << 6;
#pragma unroll
        for (int i = 0; i < 4; i++) {
            int q = tid + 256 * i;
            int r = q >> 3, u = q & 7;
            cpa16u(sptr(As + r * H_LD + u * 8), p.A + (size_t)(m0 + r) * p.lda + k0 + u * 8);
        }
#pragma unroll
        for (int i = 0; i < 4; i++) {
            int q = tid + 256 * i;
            int r = q >> 3, u = q & 7;
            cpa16u(sptr(Bs + r * H_LD + u * 8), p.Bm + (size_t)(n0 + r) * p.ldb + k0 + u * 8);
        }
    };

    loadChunk(0, 0);
    asm volatile("cp.async.commit_group;\n");
    if (KT > 1) loadChunk(1, 1);
    asm volatile("cp.async.commit_group;\n");

    for (int kt = 0; kt < KT; kt++) {
        if (kt < KT - 1) { asm volatile("cp.async.wait_group 1;\n"); }
        else             { asm volatile("cp.async.wait_group 0;\n"); }
        __syncthreads();
        if (kt + 2 < KT) {
            loadChunk(kt + 2, (kt + 2) % H_NSTAGE);
            asm volatile("cp.async.commit_group;\n");
        }
        const int stg = kt % H_NSTAGE;
        __half* As = smh + stg * H_STAGE;
        __half* Bs = As + H_TILE;
#pragma unroll
        for (int kk = 0; kk < 2; kk++) { }
#pragma unroll
        for (int kk = 0; kk < 4; kk++) {
            wmma::fragment<wmma::matrix_a, 16, 16, 16, __half, wmma::row_major> af[4];
#pragma unroll
            for (int i = 0; i < 4; i++)
                wmma::load_matrix_sync(af[i], As + (wm * 64 + i * 16) * H_LD + kk * 16, H_LD);
            wmma::fragment<wmma::matrix_b, 16, 16, 16, __half, wmma::col_major> bf[2];
#pragma unroll
            for (int j = 0; j < 2; j++)
                wmma::load_matrix_sync(bf[j], Bs + (wn * 32 + j * 16) * H_LD + kk * 16, H_LD);
#pragma unroll
            for (int i = 0; i < 4; i++)
#pragma unroll
                for (int j = 0; j < 2; j++)
                    wmma::mma_sync(acc[i][j], af[i], bf[j], acc[i][j]);
        }
    }

#pragma unroll
    for (int i = 0; i < 4; i++)
#pragma unroll
        for (int j = 0; j < 2; j++)
            wmma::store_matrix_sync(p.C + (size_t)(m0 + wm * 64 + i * 16) * p.ldc + n0 + wn * 32 + j * 16,
                                    acc[i][j], p.ldc, wmma::mem_row_major);
}

// ================= tf32 GEMM (setup only) =================
struct GP {
    const float* A;
    const float* Bm;
    float* C;
    int M, N, K, lda, ldb, ldc;
};
enum { A_PLAIN = 0, A_XG = 1 };
enum { B_NK = 0, B_KN = 1 };

#define ST_A 4608
#define ST_B_NK 4608
#define ST_B_KN 4224
#define NSTAGE 3
#define SMEM_NK_BYTES (NSTAGE * (ST_A + ST_B_NK) * 4)
#define SMEM_KN_BYTES (NSTAGE * (ST_A + ST_B_KN) * 4)

template <int AMAP, int BMODE, bool ALA, bool ALB>
__global__ __launch_bounds__(256, 2) void hgemm_k(GP p0, GP p1) {
    constexpr int STB = (BMODE == B_NK) ? ST_B_NK : ST_B_KN;
    constexpr int STST = ST_A + STB;
    extern __shared__ float sm[];
    GP p = (blockIdx.z == 0) ? p0 : p1;
    const int tid = threadIdx.x;
    const int warp = tid >> 5;
    const int wm = warp & 1;
    const int wn = warp >> 1;
    const int m0 = blockIdx.x * 128, n0 = blockIdx.y * 128;
    const int KT = (p.K + 31) >> 5;

    wmma::fragment<wmma::accumulator, 16, 16, 8, float> acc[4][2];
#pragma unroll
    for (int i = 0; i < 4; i++)
#pragma unroll
        for (int j = 0; j < 2; j++) wmma::fill_fragment(acc[i][j], 0.f);

    auto loadTile = [&](int kt, int stg) {
        float* As = sm + stg * STST;
        float* Bs = As + ST_A;
        const int k0 = kt << 5;
        if (ALA) {
#pragma unroll
            for (int i = 0; i < 4; i++) {
                int c = tid + 256 * i;
                int m = c >> 3, kq = c & 7;
                int gm = m0 + m, gk = k0 + kq * 4;
                bool pr = (gm < p.M) && (gk < p.K);
                const float* src = pr ? (p.A + (size_t)gm * p.lda + gk) : p.A;
                cpa16(sptr(As + m * 36 + kq * 4), src, pr);
            }
        } else {
#pragma unroll
            for (int i = 0; i < 16; i++) {
                int idx = tid + 256 * i;
                int m = idx >> 5, k = idx & 31;
                int gm = m0 + m, gk = k0 + k;
                bool pr = (gm < p.M) && (gk < p.K);
                const float* src = p.A;
                if (pr) {
                    size_t off;
                    if (AMAP == A_XG) { int t = gm / BB, b = gm % BB; off = (size_t)b * (TIN * PP) + (size_t)t * PP + gk; }
                    else off = (size_t)gm * p.lda + gk;
                    src = p.A + off;
                }
                cpa4(sptr(As + m * 36 + k), src, pr);
            }
        }
        if (BMODE == B_NK) {
            if (ALB) {
#pragma unroll
                for (int i = 0; i < 4; i++) {
                    int c = tid + 256 * i;
                    int n = c >> 3, kq = c & 7;
                    int gn = n0 + n, gk = k0 + kq * 4;
                    bool pr = (gn < p.N) && (gk < p.K);
                    const float* src = pr ? (p.Bm + (size_t)gn * p.ldb + gk) : p.Bm;
                    cpa16(sptr(Bs + n * 36 + kq * 4), src, pr);
                }
            } else {
#pragma unroll
                for (int i = 0; i < 16; i++) {
                    int idx = tid + 256 * i;
                    int n = idx >> 5, k = idx & 31;
                    int gn = n0 + n, gk = k0 + k;
                    bool pr = (gn < p.N) && (gk < p.K);
                    const float* src = pr ? (p.Bm + (size_t)gn * p.ldb + gk) : p.Bm;
                    cpa4(sptr(Bs + n * 36 + k), src, pr);
                }
            }
        } else {
            if (ALB) {
#pragma unroll
                for (int i = 0; i < 4; i++) {
                    int c = tid + 256 * i;
                    int k = c >> 5, nq = c & 31;
                    int gk = k0 + k, gn = n0 + nq * 4;
                    bool pr = (gk < p.K) && (gn < p.N);
                    const float* src = pr ? (p.Bm + (size_t)gk * p.ldb + gn) : p.Bm;
                    cpa16(sptr(Bs + k * 132 + nq * 4), src, pr);
                }
            } else {
#pragma unroll
                for (int i = 0; i < 16; i++) {
                    int idx = tid + 256 * i;
                    int k = idx >> 7, n = idx & 127;
                    int gk = k0 + k, gn = n0 + n;
                    bool pr = (gk < p.K) && (gn < p.N);
                    const float* src = pr ? (p.Bm + (size_t)gk * p.ldb + gn) : p.Bm;
                    cpa4(sptr(Bs + k * 132 + n), src, pr);
                }
            }
        }
    };

    loadTile(0, 0);
    asm volatile("cp.async.commit_group;\n");
    if (KT > 1) loadTile(1, 1);
    asm volatile("cp.async.commit_group;\n");

    for (int kt = 0; kt < KT; kt++) {
        if (kt < KT - 1) { asm volatile("cp.async.wait_group 1;\n"); }
        else             { asm volatile("cp.async.wait_group 0;\n"); }
        __syncthreads();
        if (kt + 2 < KT) {
            loadTile(kt + 2, (kt + 2) % NSTAGE);
            asm volatile("cp.async.commit_group;\n");
        }
        const int stg = kt % NSTAGE;
        float* As = sm + stg * STST;
        float* Bs = As + ST_A;
#pragma unroll
        for (int kk = 0; kk < 4; kk++) {
            wmma::fragment<wmma::matrix_a, 16, 16, 8, wmma::precision::tf32, wmma::row_major> af[4];
#pragma unroll
            for (int i = 0; i < 4; i++)
                wmma::load_matrix_sync(af[i], As + (wm * 64 + i * 16) * 36 + kk * 8, 36);
            if (BMODE == B_NK) {
                wmma::fragment<wmma::matrix_b, 16, 16, 8, wmma::precision::tf32, wmma::col_major> bf[2];
#pragma unroll
                for (int j = 0; j < 2; j++)
                    wmma::load_matrix_sync(bf[j], Bs + (wn * 32 + j * 16) * 36 + kk * 8, 36);
#pragma unroll
                for (int i = 0; i < 4; i++)
#pragma unroll
                    for (int j = 0; j < 2; j++)
                        wmma::mma_sync(acc[i][j], af[i], bf[j], acc[i][j]);
            } else {
                wmma::fragment<wmma::matrix_b, 16, 16, 8, wmma::precision::tf32, wmma::row_major> bf[2];
#pragma unroll
                for (int j = 0; j < 2; j++)
                    wmma::load_matrix_sync(bf[j], Bs + (kk * 8) * 132 + wn * 32 + j * 16, 132);
#pragma unroll
                for (int i = 0; i < 4; i++)
#pragma unroll
                    for (int j = 0; j < 2; j++)
                        wmma::mma_sync(acc[i][j], af[i], bf[j], acc[i][j]);
            }
        }
    }

#pragma unroll
    for (int i = 0; i < 4; i++)
#pragma unroll
        for (int j = 0; j < 2; j++)
            wmma::store_matrix_sync(p.C + (size_t)(m0 + wm * 64 + i * 16) * p.ldc + n0 + wn * 32 + j * 16,
                                    acc[i][j], p.ldc, wmma::mem_row_major);
}

// ================= LSTM pointwise cell (vectorized, fast transcendentals) =================
struct CP {
    const float* mm;
    const float* pre;
    const float* bias;
    const float* cprev;
    float* cout;
    __half* hout16;
};

__global__ void lstm_cell_k(CP pa, CP pb, int first) {
    CP p = blockIdx.y ? pb : pa;
    int idx = blockIdx.x * blockDim.x + threadIdx.x;   // over BB*HH/4
    if (idx >= BB * HH / 4) return;
    int b = idx >> 8, u = (idx & 255) * 4;
    const float* g = p.mm + (size_t)b * GG;
    float4 gi = *(const float4*)(g + u);
    float4 gf = *(const float4*)(g + HH + u);
    float4 gc = *(const float4*)(g + 2 * HH + u);
    float4 go = *(const float4*)(g + 3 * HH + u);
    float* giA = (float*)&gi; float* gfA = (float*)&gf;
    float* gcA = (float*)&gc; float* goA = (float*)&go;
    if (p.pre) {
        const float* q = p.pre + (size_t)b * GG;
        float4 pi = *(const float4*)(q + u), pf = *(const float4*)(q + HH + u);
        float4 pc = *(const float4*)(q + 2 * HH + u), po = *(const float4*)(q + 3 * HH + u);
        float* a = (float*)&pi; float* bb2 = (float*)&pf; float* c2 = (float*)&pc; float* d2 = (float*)&po;
#pragma unroll
        for (int k = 0; k < 4; k++) { giA[k] += a[k]; gfA[k] += bb2[k]; gcA[k] += c2[k]; goA[k] += d2[k]; }
    }
    {
        float4 bi = *(const float4*)(p.bias + u), bf4 = *(const float4*)(p.bias + HH + u);
        float4 bc = *(const float4*)(p.bias + 2 * HH + u), bo = *(const float4*)(p.bias + 3 * HH + u);
        float* a = (float*)&bi; float* bb2 = (float*)&bf4; float* c2 = (float*)&bc; float* d2 = (float*)&bo;
#pragma unroll
        for (int k = 0; k < 4; k++) { giA[k] += a[k]; gfA[k] += bb2[k]; gcA[k] += c2[k]; goA[k] += d2[k]; }
    }
    float4 cv = first ? make_float4(0.f, 0.f, 0.f, 0.f) : *(const float4*)(p.cprev + (size_t)b * HH + u);
    float* cA = (float*)&cv;
    float4 cn4; float* cnA = (float*)&cn4;
    float hn[4];
#pragma unroll
    for (int k = 0; k < 4; k++) {
        float si = sigma(giA[k]), sf = sigma(gfA[k]), so = sigma(goA[k]);
        float cn = sf * cA[k] + si * tanha(gcA[k]);
        cnA[k] = cn;
        hn[k] = so * tanha(cn);
    }
    *(float4*)(p.cout + (size_t)b * HH + u) = cn4;
    __half2* hp = (__half2*)(p.hout16 + (size_t)b * HH + u);
    hp[0] = __floats2half2_rn(hn[0], hn[1]);
    hp[1] = __floats2half2_rn(hn[2], hn[3]);
}

// ================= standalone attention (decoder t=0 only), vectorized =================
__global__ void attention_k(const __half* __restrict__ allh16, const __half* __restrict__ allhz16,
                            const __half* __restrict__ hprev16, const float* __restrict__ cvec,
                            __half* __restrict__ hcat16) {
    int b = blockIdx.x;
    int tid = threadIdx.x, lane = tid & 31, w = tid >> 5;
    __shared__ float sc[21];
    __shared__ float wts[21];
    const float* cb = cvec + (size_t)b * HH;

    for (int s = w; s < 21; s += 8) {
        const __half* hs = (s < TIN)  ? (allh16 + ((size_t)s * BB + b) * HH)
                         : (s == TIN) ? (hprev16 + (size_t)b * HH)
                                      : (allhz16 + ((size_t)(s - TIN - 1) * BB + b) * HH);
        float part = 0.f;
        for (int q = lane; q < 128; q += 32)
            part += dot8(((const float4*)hs)[q], ((const float4*)cb)[2 * q], ((const float4*)cb)[2 * q + 1]);
#pragma unroll
        for (int off = 16; off; off >>= 1) part += __shfl_down_sync(0xffffffffu, part, off);
        if (lane == 0) sc[s] = part;
    }
    __syncthreads();
    if (tid == 0) {
        float mx = sc[0];
        for (int s = 1; s < 21; s++) mx = fmaxf(mx, sc[s]);
        float sum = 0.f;
        for (int s = 0; s < 21; s++) { float e = expf(sc[s] - mx); wts[s] = e; sum += e; }
        float inv = 1.f / sum;
        for (int s = 0; s < 21; s++) wts[s] *= inv;
    }
    __syncthreads();
    __half* out = hcat16 + (size_t)b * 2048;
    const __half* hp = hprev16 + (size_t)b * HH;
    {   // pass 2: 256 threads x 4 halfs
        int q = tid;
        float a0 = 0.f, a1 = 0.f, a2 = 0.f, a3 = 0.f;
#pragma unroll
        for (int s = 0; s < 21; s++) {
            const __half* hs = (s < TIN)  ? (allh16 + ((size_t)s * BB + b) * HH)
                             : (s == TIN) ? hp
                                          : (allhz16 + ((size_t)(s - TIN - 1) * BB + b) * HH);
            float2 hv = ((const float2*)hs)[q];
            const __half2* h2 = (const __half2*)&hv;
            float2 x0 = __half22float2(h2[0]), x1 = __half22float2(h2[1]);
            float wv = wts[s];
            a0 += wv * x0.x; a1 += wv * x0.y; a2 += wv * x1.x; a3 += wv * x1.y;
        }
        ((__half2*)out)[2 * q] = __floats2half2_rn(a0, a1);
        ((__half2*)out)[2 * q + 1] = __floats2half2_rn(a2, a3);
        ((float2*)(out + HH))[q] = ((const float2*)hp)[q];
    }
}

// ================= fused decoder cell(t) + attention(t+1), vectorized =================
__global__ void cellatt_k(const float* __restrict__ gates, const float* __restrict__ bias,
                          const float* __restrict__ cprev,
                          float* __restrict__ cout, __half* __restrict__ hout16,
                          const __half* __restrict__ allh16, const __half* __restrict__ allhz16,
                          __half* __restrict__ hcat16) {
    __shared__ __align__(16) float cs[1024];
    __shared__ __align__(16) __half hs16[1024];
    __shared__ float sc[21];
    __shared__ float wts[21];
    int b = blockIdx.x;
    int tid = threadIdx.x, lane = tid & 31, w = tid >> 5;

    // ---- LSTM cell: each thread 4 consecutive units ----
    {
        int u = tid * 4;
        const float* g = gates + (size_t)b * GG;
        float4 gi = *(const float4*)(g + u);
        float4 gf = *(const float4*)(g + HH + u);
        float4 gc = *(const float4*)(g + 2 * HH + u);
        float4 go = *(const float4*)(g + 3 * HH + u);
        float4 bi = *(const float4*)(bias + u), bf4 = *(const float4*)(bias + HH + u);
        float4 bc = *(const float4*)(bias + 2 * HH + u), bo = *(const float4*)(bias + 3 * HH + u);
        float4 cv = *(const float4*)(cprev + (size_t)b * HH + u);
        float* giA = (float*)&gi; float* gfA = (float*)&gf; float* gcA = (float*)&gc; float* goA = (float*)&go;
        float* biA = (float*)&bi; float* bfA = (float*)&bf4; float* bcA = (float*)&bc; float* boA = (float*)&bo;
        float* cA = (float*)&cv;
        float4 cn4; float* cnA = (float*)&cn4;
        float hn[4];
#pragma unroll
        for (int k = 0; k < 4; k++) {
            float si = sigma(giA[k] + biA[k]);
            float sf = sigma(gfA[k] + bfA[k]);
            float so = sigma(goA[k] + boA[k]);
            float cn = sf * cA[k] + si * tanha(gcA[k] + bcA[k]);
            cnA[k] = cn;
            hn[k] = so * tanha(cn);
        }
        *(float4*)(cout + (size_t)b * HH + u) = cn4;
        __half2 h01 = __floats2half2_rn(hn[0], hn[1]);
        __half2 h23 = __floats2half2_rn(hn[2], hn[3]);
        __half2* hp = (__half2*)(hout16 + (size_t)b * HH + u);
        hp[0] = h01; hp[1] = h23;
        *(float4*)(cs + u) = cn4;
        ((__half2*)hs16)[2 * tid] = h01;
        ((__half2*)hs16)[2 * tid + 1] = h23;
    }
    __syncthreads();

    // ---- attention pass 1 (query = fresh c from smem) ----
    for (int s = w; s < 21; s += 8) {
        float part = 0.f;
        const __half* hs = (s == TIN) ? hs16
                         : (s < TIN)  ? (allh16 + ((size_t)s * BB + b) * HH)
                                      : (allhz16 + ((size_t)(s - TIN - 1) * BB + b) * HH);
        for (int q = lane; q < 128; q += 32)
            part += dot8(((const float4*)hs)[q], ((const float4*)cs)[2 * q], ((const float4*)cs)[2 * q + 1]);
#pragma unroll
        for (int off = 16; off; off >>= 1) part += __shfl_down_sync(0xffffffffu, part, off);
        if (lane == 0) sc[s] = part;
    }
    __syncthreads();
    if (tid == 0) {
        float mx = sc[0];
        for (int s = 1; s < 21; s++) mx = fmaxf(mx, sc[s]);
        float sum = 0.f;
        for (int s = 0; s < 21; s++) { float e = expf(sc[s] - mx); wts[s] = e; sum += e; }
        float inv = 1.f / sum;
        for (int s = 0; s < 21; s++) wts[s] *= inv;
    }
    __syncthreads();
    __half* out = hcat16 + (size_t)b * 2048;
    {   // pass 2: 256 threads x 4 halfs
        int q = tid;
        float a0 = 0.f, a1 = 0.f, a2 = 0.f, a3 = 0.f;
#pragma unroll
        for (int s = 0; s < 21; s++) {
            const __half* hs = (s == TIN) ? hs16
                             : (s < TIN)  ? (allh16 + ((size_t)s * BB + b) * HH)
                                          : (allhz16 + ((size_t)(s - TIN - 1) * BB + b) * HH);
            float2 hv = ((const float2*)hs)[q];
            const __half2* h2 = (const __half2*)&hv;
            float2 x0 = __half22float2(h2[0]), x1 = __half22float2(h2[1]);
            float wv = wts[s];
            a0 += wv * x0.x; a1 += wv * x0.y; a2 += wv * x1.x; a3 += wv * x1.y;
        }
        ((__half2*)out)[2 * q] = __floats2half2_rn(a0, a1);
        ((__half2*)out)[2 * q + 1] = __floats2half2_rn(a2, a3);
        ((float2*)(out + HH))[q] = ((const float2*)hs16)[q];
    }
}

// ================= small setup kernels =================
__global__ void prep_bias2_k(const float* wihA, const float* vecA, const float* b1A, const float* b2A, float* outA,
                             const float* wihB, const float* vecB, const float* b1B, const float* b2B, float* outB) {
    const float* wih = blockIdx.y ? wihB : wihA;
    const float* vec = blockIdx.y ? vecB : vecA;
    const float* b1  = blockIdx.y ? b1B  : b1A;
    const float* b2  = blockIdx.y ? b2B  : b2A;
    float* out       = blockIdx.y ? outB : outA;
    int wid = (blockIdx.x * blockDim.x + threadIdx.x) >> 5;
    int lane = threadIdx.x & 31;
    if (wid >= GG) return;
    const float* row = wih + (size_t)wid * DD;
    float s = 0.f;
    for (int d = lane; d < DD; d += 32) s += row[d] * vec[d];
#pragma unroll
    for (int off = 16; off; off >>= 1) s += __shfl_down_sync(0xffffffffu, s, off);
    if (lane == 0) out[wid] = b1[wid] + b2[wid] + s;
}

__global__ void f2h2_k(const float* __restrict__ s0, __half* __restrict__ d0,
                       const float* __restrict__ s1, __half* __restrict__ d1, int n) {
    int i = blockIdx.x * blockDim.x + threadIdx.x;
    const float* s = blockIdx.y ? s1 : s0;
    __half* d = blockIdx.y ? d1 : d0;
    if (i < n) d[i] = __float2half(s[i]);
}

__global__ void pack_wcat16_k(const float* __restrict__ whh, const float* __restrict__ weff) {
    size_t idx = (size_t)blockIdx.x * blockDim.x + threadIdx.x;
    if (idx >= (size_t)GG * 2048) return;
    int j = (int)(idx >> 11), m = (int)(idx & 2047);
    float v = (m < 1024) ? whh[(size_t)j * 1024 + m] : weff[(size_t)j * 1024 + (m - 1024)];
    d_Wcat16[idx] = __float2half(v);
}

__global__ void pack_posew16_k(const float* __restrict__ pw) {
    int idx = blockIdx.x * blockDim.x + threadIdx.x;
    if (idx >= 128 * HH) return;
    int r = idx >> 10, c = idx & 1023;
    d_poseW16[idx] = (r < PP) ? __float2half(pw[r * HH + c]) : __half(0);
}

__global__ void pose_fin_k(const float* __restrict__ pc, const float* __restrict__ pb,
                           float* __restrict__ out) {
    int idx = blockIdx.x * blockDim.x + threadIdx.x;
    if (idx >= BB * TOUT * PP) return;
    int pp = idx % PP;
    int bt = idx / PP;
    int t = bt % TOUT, b = bt / TOUT;
    out[idx] = pc[((size_t)t * BB + b) * 128 + pp] + pb[pp];
}

// ================= host orchestration =================
extern "C" void kernel_launch(void* const* d_in, const int* in_sizes, int n_in,
                              void* d_out, int out_size) {
    const float* x        = (const float*)d_in[0];
    const float* z        = (const float*)d_in[1];
    const float* wf       = (const float*)d_in[2];
    const float* bf       = (const float*)d_in[3];
    const float* enc_wih  = (const float*)d_in[4];
    const float* enc_whh  = (const float*)d_in[5];
    const float* enc_bih  = (const float*)d_in[6];
    const float* enc_bhh  = (const float*)d_in[7];
    const float* encp_wih = (const float*)d_in[8];
    const float* encp_whh = (const float*)d_in[9];
    const float* encp_bih = (const float*)d_in[10];
    const float* encp_bhh = (const float*)d_in[11];
    const float* dec_wih  = (const float*)d_in[12];
    const float* dec_whh  = (const float*)d_in[13];
    const float* dec_bih  = (const float*)d_in[14];
    const float* dec_bhh  = (const float*)d_in[15];
    const float* lin_w    = (const float*)d_in[16];
    const float* lin_b    = (const float*)d_in[17];
    const float* pose_w   = (const float*)d_in[18];
    const float* pose_b   = (const float*)d_in[19];
    float* out = (float*)d_out;

    void* pv;
    cudaGetSymbolAddress(&pv, d_WcombX);  float* WcombX  = (float*)pv;
    cudaGetSymbolAddress(&pv, d_WcombZ);  float* WcombZ  = (float*)pv;
    cudaGetSymbolAddress(&pv, d_bcombX);  float* bcombX  = (float*)pv;
    cudaGetSymbolAddress(&pv, d_bcombZ);  float* bcombZ  = (float*)pv;
    cudaGetSymbolAddress(&pv, d_WeffF);   float* WeffF   = (float*)pv;
    cudaGetSymbolAddress(&pv, d_Wcat16);  __half* Wcat16 = (__half*)pv;
    cudaGetSymbolAddress(&pv, d_whhX16);  __half* whhX16 = (__half*)pv;
    cudaGetSymbolAddress(&pv, d_whhZ16);  __half* whhZ16 = (__half*)pv;
    cudaGetSymbolAddress(&pv, d_poseW16); __half* poseW16 = (__half*)pv;
    cudaGetSymbolAddress(&pv, d_bcat);    float* bcat    = (float*)pv;
    cudaGetSymbolAddress(&pv, d_ginX);    float* ginX    = (float*)pv;
    cudaGetSymbolAddress(&pv, d_ginZ);    float* ginZ    = (float*)pv;
    cudaGetSymbolAddress(&pv, d_allh16X); __half* allh16X = (__half*)pv;
    cudaGetSymbolAddress(&pv, d_allh16Z); __half* allh16Z = (__half*)pv;
    cudaGetSymbolAddress(&pv, d_cX);      float* cX      = (float*)pv;
    cudaGetSymbolAddress(&pv, d_cZ);      float* cZ      = (float*)pv;
    cudaGetSymbolAddress(&pv, d_decc);    float* decc    = (float*)pv;
    cudaGetSymbolAddress(&pv, d_gates);   float* gates   = (float*)pv;
    cudaGetSymbolAddress(&pv, d_hcat16);  __half* hcat16 = (__half*)pv;
    cudaGetSymbolAddress(&pv, d_dechs16); __half* dechs16 = (__half*)pv;
    cudaGetSymbolAddress(&pv, d_poseC);   float* poseC   = (float*)pv;

    cudaFuncSetAttribute(hgemm_k<A_PLAIN, B_KN, true, false>, cudaFuncAttributeMaxDynamicSharedMemorySize, SMEM_KN_BYTES);
    cudaFuncSetAttribute(hgemm_k<A_XG,    B_NK, false, true>, cudaFuncAttributeMaxDynamicSharedMemorySize, SMEM_NK_BYTES);
    cudaFuncSetAttribute(hgemm_k<A_PLAIN, B_KN, true, true>,  cudaFuncAttributeMaxDynamicSharedMemorySize, SMEM_KN_BYTES);
    cudaFuncSetAttribute(hgemm16_k, cudaFuncAttributeMaxDynamicSharedMemorySize, H_SMEM_BYTES);

    // ---- Wcomb = enc_wih @ wf (tf32, both encoders) ----
    {
        GP p0 = {enc_wih,  wf, WcombX, GG, PP, DD, DD, PP, 256};
        GP p1 = {encp_wih, wf, WcombZ, GG, PP, DD, DD, PP, 256};
        hgemm_k<A_PLAIN, B_KN, true, false><<<dim3(GG / 128, 1, 2), 256, SMEM_KN_BYTES>>>(p0, p1);
    }
    // ---- gin = x @ Wcomb^T (tf32, both encoders) ----
    {
        GP p0 = {x, WcombX, ginX, TIN * BB, GG, PP, PP, 256, GG};
        GP p1 = {z, WcombZ, ginZ, TIN * BB, GG, PP, PP, 256, GG};
        hgemm_k<A_XG, B_NK, false, true><<<dim3(TIN * BB / 128, GG / 128, 2), 256, SMEM_NK_BYTES>>>(p0, p1);
    }
    // ---- whh -> fp16 (both encoders, one launch) ----
    f2h2_k<<<dim3((GG * HH + 255) / 256, 2), 256>>>(enc_whh, whhX16, encp_whh, whhZ16, GG * HH);
    // ---- folded biases (both encoders, one launch) ----
    prep_bias2_k<<<dim3(512, 2), 256>>>(enc_wih, bf, enc_bih, enc_bhh, bcombX,
                                        encp_wih, bf, encp_bih, encp_bhh, bcombZ);

    // ---- encoder t=0 ----
    {
        CP pa = {ginX, nullptr, bcombX, nullptr, cX, allh16X};
        CP pb = {ginZ, nullptr, bcombZ, nullptr, cZ, allh16Z};
        lstm_cell_k<<<dim3(1024, 2), 256>>>(pa, pb, 1);
    }
    // ---- encoder recurrence (fp16 GEMM) ----
    for (int t = 1; t < TIN; t++) {
        GP16 p0 = {allh16X + (size_t)(t - 1) * BB * HH, whhX16, gates,                   BB, GG, HH, HH, HH, GG};
        GP16 p1 = {allh16Z + (size_t)(t - 1) * BB * HH, whhZ16, gates + (size_t)BB * GG, BB, GG, HH, HH, HH, GG};
        hgemm16_k<<<dim3(BB / 128, GG / 128, 2), 256, H_SMEM_BYTES>>>(p0, p1);
        CP pa = {gates,                   ginX + (size_t)t * BB * GG, bcombX, cX, cX, allh16X + (size_t)t * BB * HH};
        CP pb = {gates + (size_t)BB * GG, ginZ + (size_t)t * BB * GG, bcombZ, cZ, cZ, allh16Z + (size_t)t * BB * HH};
        lstm_cell_k<<<dim3(1024, 2), 256>>>(pa, pb, 0);
    }

    // ---- decoder setup ----
    {   // Weff = dec_wih @ lin_w (tf32, f32 out)
        GP p0 = {dec_wih, lin_w, WeffF, GG, HH, DD, DD, HH, HH};
        hgemm_k<A_PLAIN, B_KN, true, true><<<dim3(GG / 128, HH / 128, 1), 256, SMEM_KN_BYTES>>>(p0, p0);
    }
    pack_wcat16_k<<<(int)(((size_t)GG * 2048 + 255) / 256), 256>>>(dec_whh, WeffF);
    pack_posew16_k<<<(128 * HH + 255) / 256, 256>>>(pose_w);
    prep_bias2_k<<<dim3(512, 1), 256>>>(dec_wih, lin_b, dec_bih, dec_bhh, bcat,
                                        dec_wih, lin_b, dec_bih, dec_bhh, bcat);

    // ---- decoder: attention(0) standalone, then GEMM + fused(cell+next attention) ----
    attention_k<<<BB, 256>>>(allh16X, allh16Z,
                             allh16X + (size_t)(TIN - 1) * BB * HH, cX, hcat16);
    for (int t = 0; t < TOUT; t++) {
        GP16 p0 = {hcat16, Wcat16, gates, BB, GG, 2048, 2048, 2048, GG};
        hgemm16_k<<<dim3(BB / 128, GG / 128, 1), 256, H_SMEM_BYTES>>>(p0, p0);
        const float* cptr = (t == 0) ? cX : decc;
        if (t < TOUT - 1) {
            cellatt_k<<<BB, 256>>>(gates, bcat, cptr, decc,
                                   dechs16 + (size_t)t * BB * HH,
                                   allh16X, allh16Z, hcat16);
        } else {
            CP pa = {gates, nullptr, bcat, cptr, decc, dechs16 + (size_t)t * BB * HH};
            lstm_cell_k<<<dim3(1024, 1), 256>>>(pa, pa, 0);
        }
    }

    // ---- output projection (fp16 GEMM) + epilogue ----
    {
        GP16 p0 = {dechs16, poseW16, poseC, TOUT * BB, 128, HH, HH, HH, 128};
        hgemm16_k<<<dim3(TOUT * BB / 128, 1, 1), 256, H_SMEM_BYTES>>>(p0, p0);
        pose_fin_k<<<(BB * TOUT * PP + 255) / 256, 256>>>(poseC, pose_b, out);
    }
}

// round 16
// speedup vs baseline: 1.4007x; 1.4007x over previous
#include <cuda_runtime.h>
#include <cuda_fp16.h>
#include <mma.h>
#include <math.h>

using namespace nvcuda;

#define BB 1024
#define HH 1024
#define DD 512
#define PP 66
#define TIN 10
#define TOUT 25
#define GG 4096   // 4*HH

// ---------------- static device scratch (no allocations allowed) ----------------
__device__ float d_WcombX[(size_t)GG * 256];
__device__ float d_WcombZ[(size_t)GG * 256];
__device__ float d_bcombX[GG];
__device__ float d_bcombZ[GG];
__device__ float d_WeffF[(size_t)GG * HH];             // dec_wih @ lin_w, f32
__device__ __half d_Wcat16[(size_t)GG * 2048];         // fp16: [dec_whh | Weff]
__device__ __half d_whhX16[(size_t)GG * HH];
__device__ __half d_whhZ16[(size_t)GG * HH];
__device__ float d_bcat[GG];
__device__ float d_ginX[(size_t)TIN * BB * GG];
__device__ float d_ginZ[(size_t)TIN * BB * GG];
__device__ __half d_allh16X[(size_t)TIN * BB * HH];
__device__ __half d_allh16Z[(size_t)TIN * BB * HH];
__device__ float d_cX[BB * HH];
__device__ float d_cZ[BB * HH];
__device__ float d_decc[BB * HH];
__device__ float d_gates[(size_t)2 * BB * GG];
__device__ __half d_hcat16[(size_t)BB * 2048];         // [atth | h_n] fp16
__device__ float d_dechs[(size_t)TOUT * BB * HH];      // f32 (pose GEMM input)
__device__ __half d_dechs16[(size_t)TOUT * BB * HH];   // fp16 (attention input)
__device__ float d_poseC[(size_t)TOUT * BB * 256];

// ================= helpers =================
__device__ __forceinline__ unsigned sptr(const void* p) {
    return (unsigned)__cvta_generic_to_shared(p);
}
__device__ __forceinline__ void cpa16(unsigned d, const void* s, bool pr) {
    int sz = pr ? 16 : 0;
    asm volatile("cp.async.cg.shared.global [%0], [%1], 16, %2;\n" :: "r"(d), "l"(s), "r"(sz));
}
__device__ __forceinline__ void cpa16u(unsigned d, const void* s) {
    asm volatile("cp.async.cg.shared.global [%0], [%1], 16;\n" :: "r"(d), "l"(s));
}
__device__ __forceinline__ void cpa4(unsigned d, const void* s, bool pr) {
    int sz = pr ? 4 : 0;
    asm volatile("cp.async.ca.shared.global [%0], [%1], 4, %2;\n" :: "r"(d), "l"(s), "r"(sz));
}
__device__ __forceinline__ float tanha(float x) {
    float y;
    asm("tanh.approx.f32 %0, %1;" : "=f"(y) : "f"(x));
    return y;
}
__device__ __forceinline__ float sigma(float x) {
    return 0.5f + 0.5f * tanha(0.5f * x);
}
// dot of 8 fp16 (one float4 worth) with 8 f32 (two float4)
__device__ __forceinline__ float dot8(float4 hv, float4 c0, float4 c1) {
    const __half2* h2 = (const __half2*)&hv;
    float2 a0 = __half22float2(h2[0]);
    float2 a1 = __half22float2(h2[1]);
    float2 a2 = __half22float2(h2[2]);
    float2 a3 = __half22float2(h2[3]);
    return a0.x * c0.x + a0.y * c0.y + a1.x * c0.z + a1.y * c0.w
         + a2.x * c1.x + a2.y * c1.y + a3.x * c1.z + a3.y * c1.w;
}

// ================= fp16 recurrent GEMM: 128x128 block, 64x32 warp tile, k-chunk 64 =================
struct GP16 {
    const __half* A;     // [M, K] row-major
    const __half* Bm;    // [N, K] row-major (weights)
    float* C;            // [M, N]
    int M, N, K, lda, ldb, ldc;
};

#define H_LD 72                          // halfs per smem row (64 + 8 pad)
#define H_TILE (128 * H_LD)
#define H_STAGE (2 * H_TILE)
#define H_NSTAGE 3
#define H_SMEM_BYTES (H_NSTAGE * H_STAGE * 2)   // 110592 B

__global__ __launch_bounds__(256, 2) void hgemm16_k(GP16 p0, GP16 p1) {
    extern __shared__ __half smh[];
    GP16 p = (blockIdx.z == 0) ? p0 : p1;
    const int tid = threadIdx.x;
    const int warp = tid >> 5;
    const int wm = warp & 1;             // 2 x 4 warp grid, warp tile 64m x 32n
    const int wn = warp >> 1;
    const int m0 = blockIdx.x * 128, n0 = blockIdx.y * 128;
    const int KT = p.K >> 6;             // 64-k chunks

    wmma::fragment<wmma::accumulator, 16, 16, 16, float> acc[4][2];
#pragma unroll
    for (int i = 0; i < 4; i++)
#pragma unroll
        for (int j = 0; j < 2; j++) wmma::fill_fragment(acc[i][j], 0.f);

    auto loadChunk = [&](int kt, int stg) {
        __half* As = smh + stg * H_STAGE;
        __half* Bs = As + H_TILE;
        const int k0 = kt << 6;
#pragma unroll
        for (int i = 0; i < 4; i++) {
            int q = tid + 256 * i;
            int r = q >> 3, u = q & 7;
            cpa16u(sptr(As + r * H_LD + u * 8), p.A + (size_t)(m0 + r) * p.lda + k0 + u * 8);
        }
#pragma unroll
        for (int i = 0; i < 4; i++) {
            int q = tid + 256 * i;
            int r = q >> 3, u = q & 7;
            cpa16u(sptr(Bs + r * H_LD + u * 8), p.Bm + (size_t)(n0 + r) * p.ldb + k0 + u * 8);
        }
    };

    loadChunk(0, 0);
    asm volatile("cp.async.commit_group;\n");
    if (KT > 1) loadChunk(1, 1);
    asm volatile("cp.async.commit_group;\n");

    for (int kt = 0; kt < KT; kt++) {
        if (kt < KT - 1) { asm volatile("cp.async.wait_group 1;\n"); }
        else             { asm volatile("cp.async.wait_group 0;\n"); }
        __syncthreads();
        if (kt + 2 < KT) {
            loadChunk(kt + 2, (kt + 2) % H_NSTAGE);
            asm volatile("cp.async.commit_group;\n");
        }
        const int stg = kt % H_NSTAGE;
        __half* As = smh + stg * H_STAGE;
        __half* Bs = As + H_TILE;
#pragma unroll
        for (int kk = 0; kk < 4; kk++) {
            wmma::fragment<wmma::matrix_a, 16, 16, 16, __half, wmma::row_major> af[4];
#pragma unroll
            for (int i = 0; i < 4; i++)
                wmma::load_matrix_sync(af[i], As + (wm * 64 + i * 16) * H_LD + kk * 16, H_LD);
            wmma::fragment<wmma::matrix_b, 16, 16, 16, __half, wmma::col_major> bf[2];
#pragma unroll
            for (int j = 0; j < 2; j++)
                wmma::load_matrix_sync(bf[j], Bs + (wn * 32 + j * 16) * H_LD + kk * 16, H_LD);
#pragma unroll
            for (int i = 0; i < 4; i++)
#pragma unroll
                for (int j = 0; j < 2; j++)
                    wmma::mma_sync(acc[i][j], af[i], bf[j], acc[i][j]);
        }
    }

#pragma unroll
    for (int i = 0; i < 4; i++)
#pragma unroll
        for (int j = 0; j < 2; j++)
            wmma::store_matrix_sync(p.C + (size_t)(m0 + wm * 64 + i * 16) * p.ldc + n0 + wn * 32 + j * 16,
                                    acc[i][j], p.ldc, wmma::mem_row_major);
}

// ================= tf32 GEMM (setup + pose only) =================
struct GP {
    const float* A;
    const float* Bm;
    float* C;
    int M, N, K, lda, ldb, ldc;
};
enum { A_PLAIN = 0, A_XG = 1 };
enum { B_NK = 0, B_KN = 1 };

#define ST_A 4608
#define ST_B_NK 4608
#define ST_B_KN 4224
#define NSTAGE 3
#define SMEM_NK_BYTES (NSTAGE * (ST_A + ST_B_NK) * 4)
#define SMEM_KN_BYTES (NSTAGE * (ST_A + ST_B_KN) * 4)

template <int AMAP, int BMODE, bool ALA, bool ALB>
__global__ __launch_bounds__(256, 2) void hgemm_k(GP p0, GP p1) {
    constexpr int STB = (BMODE == B_NK) ? ST_B_NK : ST_B_KN;
    constexpr int STST = ST_A + STB;
    extern __shared__ float sm[];
    GP p = (blockIdx.z == 0) ? p0 : p1;
    const int tid = threadIdx.x;
    const int warp = tid >> 5;
    const int wm = warp & 1;
    const int wn = warp >> 1;
    const int m0 = blockIdx.x * 128, n0 = blockIdx.y * 128;
    const int KT = (p.K + 31) >> 5;

    wmma::fragment<wmma::accumulator, 16, 16, 8, float> acc[4][2];
#pragma unroll
    for (int i = 0; i < 4; i++)
#pragma unroll
        for (int j = 0; j < 2; j++) wmma::fill_fragment(acc[i][j], 0.f);

    auto loadTile = [&](int kt, int stg) {
        float* As = sm + stg * STST;
        float* Bs = As + ST_A;
        const int k0 = kt << 5;
        if (ALA) {
#pragma unroll
            for (int i = 0; i < 4; i++) {
                int c = tid + 256 * i;
                int m = c >> 3, kq = c & 7;
                int gm = m0 + m, gk = k0 + kq * 4;
                bool pr = (gm < p.M) && (gk < p.K);
                const float* src = pr ? (p.A + (size_t)gm * p.lda + gk) : p.A;
                cpa16(sptr(As + m * 36 + kq * 4), src, pr);
            }
        } else {
#pragma unroll
            for (int i = 0; i < 16; i++) {
                int idx = tid + 256 * i;
                int m = idx >> 5, k = idx & 31;
                int gm = m0 + m, gk = k0 + k;
                bool pr = (gm < p.M) && (gk < p.K);
                const float* src = p.A;
                if (pr) {
                    size_t off;
                    if (AMAP == A_XG) { int t = gm / BB, b = gm % BB; off = (size_t)b * (TIN * PP) + (size_t)t * PP + gk; }
                    else off = (size_t)gm * p.lda + gk;
                    src = p.A + off;
                }
                cpa4(sptr(As + m * 36 + k), src, pr);
            }
        }
        if (BMODE == B_NK) {
            if (ALB) {
#pragma unroll
                for (int i = 0; i < 4; i++) {
                    int c = tid + 256 * i;
                    int n = c >> 3, kq = c & 7;
                    int gn = n0 + n, gk = k0 + kq * 4;
                    bool pr = (gn < p.N) && (gk < p.K);
                    const float* src = pr ? (p.Bm + (size_t)gn * p.ldb + gk) : p.Bm;
                    cpa16(sptr(Bs + n * 36 + kq * 4), src, pr);
                }
            } else {
#pragma unroll
                for (int i = 0; i < 16; i++) {
                    int idx = tid + 256 * i;
                    int n = idx >> 5, k = idx & 31;
                    int gn = n0 + n, gk = k0 + k;
                    bool pr = (gn < p.N) && (gk < p.K);
                    const float* src = pr ? (p.Bm + (size_t)gn * p.ldb + gk) : p.Bm;
                    cpa4(sptr(Bs + n * 36 + k), src, pr);
                }
            }
        } else {
            if (ALB) {
#pragma unroll
                for (int i = 0; i < 4; i++) {
                    int c = tid + 256 * i;
                    int k = c >> 5, nq = c & 31;
                    int gk = k0 + k, gn = n0 + nq * 4;
                    bool pr = (gk < p.K) && (gn < p.N);
                    const float* src = pr ? (p.Bm + (size_t)gk * p.ldb + gn) : p.Bm;
                    cpa16(sptr(Bs + k * 132 + nq * 4), src, pr);
                }
            } else {
#pragma unroll
                for (int i = 0; i < 16; i++) {
                    int idx = tid + 256 * i;
                    int k = idx >> 7, n = idx & 127;
                    int gk = k0 + k, gn = n0 + n;
                    bool pr = (gk < p.K) && (gn < p.N);
                    const float* src = pr ? (p.Bm + (size_t)gk * p.ldb + gn) : p.Bm;
                    cpa4(sptr(Bs + k * 132 + n), src, pr);
                }
            }
        }
    };

    loadTile(0, 0);
    asm volatile("cp.async.commit_group;\n");
    if (KT > 1) loadTile(1, 1);
    asm volatile("cp.async.commit_group;\n");

    for (int kt = 0; kt < KT; kt++) {
        if (kt < KT - 1) { asm volatile("cp.async.wait_group 1;\n"); }
        else             { asm volatile("cp.async.wait_group 0;\n"); }
        __syncthreads();
        if (kt + 2 < KT) {
            loadTile(kt + 2, (kt + 2) % NSTAGE);
            asm volatile("cp.async.commit_group;\n");
        }
        const int stg = kt % NSTAGE;
        float* As = sm + stg * STST;
        float* Bs = As + ST_A;
#pragma unroll
        for (int kk = 0; kk < 4; kk++) {
            wmma::fragment<wmma::matrix_a, 16, 16, 8, wmma::precision::tf32, wmma::row_major> af[4];
#pragma unroll
            for (int i = 0; i < 4; i++)
                wmma::load_matrix_sync(af[i], As + (wm * 64 + i * 16) * 36 + kk * 8, 36);
            if (BMODE == B_NK) {
                wmma::fragment<wmma::matrix_b, 16, 16, 8, wmma::precision::tf32, wmma::col_major> bf[2];
#pragma unroll
                for (int j = 0; j < 2; j++)
                    wmma::load_matrix_sync(bf[j], Bs + (wn * 32 + j * 16) * 36 + kk * 8, 36);
#pragma unroll
                for (int i = 0; i < 4; i++)
#pragma unroll
                    for (int j = 0; j < 2; j++)
                        wmma::mma_sync(acc[i][j], af[i], bf[j], acc[i][j]);
            } else {
                wmma::fragment<wmma::matrix_b, 16, 16, 8, wmma::precision::tf32, wmma::row_major> bf[2];
#pragma unroll
                for (int j = 0; j < 2; j++)
                    wmma::load_matrix_sync(bf[j], Bs + (kk * 8) * 132 + wn * 32 + j * 16, 132);
#pragma unroll
                for (int i = 0; i < 4; i++)
#pragma unroll
                    for (int j = 0; j < 2; j++)
                        wmma::mma_sync(acc[i][j], af[i], bf[j], acc[i][j]);
            }
        }
    }

#pragma unroll
    for (int i = 0; i < 4; i++)
#pragma unroll
        for (int j = 0; j < 2; j++)
            wmma::store_matrix_sync(p.C + (size_t)(m0 + wm * 64 + i * 16) * p.ldc + n0 + wn * 32 + j * 16,
                                    acc[i][j], p.ldc, wmma::mem_row_major);
}

// ================= LSTM pointwise cell (fast transcendentals) =================
struct CP {
    const float* mm;
    const float* pre;
    const float* bias;
    const float* cprev;
    float* cout;
    float* hout;         // optional f32 h
    __half* hout16;      // optional fp16 h
};

__global__ void lstm_cell_k(CP pa, CP pb, int first) {
    CP p = blockIdx.y ? pb : pa;
    int idx = blockIdx.x * blockDim.x + threadIdx.x;
    if (idx >= BB * HH) return;
    int b = idx >> 10, u = idx & 1023;
    const float* g = p.mm + (size_t)b * GG;
    float gi = g[u], gf = g[HH + u], gc = g[2 * HH + u], go = g[3 * HH + u];
    if (p.pre) {
        const float* q = p.pre + (size_t)b * GG;
        gi += q[u]; gf += q[HH + u]; gc += q[2 * HH + u]; go += q[3 * HH + u];
    }
    if (p.bias) {
        gi += p.bias[u]; gf += p.bias[HH + u]; gc += p.bias[2 * HH + u]; go += p.bias[3 * HH + u];
    }
    float c = first ? 0.f : p.cprev[idx];
    float si = sigma(gi);
    float sf = sigma(gf);
    float so = sigma(go);
    float cn = sf * c + si * tanha(gc);
    float hn = so * tanha(cn);
    p.cout[idx] = cn;
    if (p.hout) p.hout[idx] = hn;
    if (p.hout16) p.hout16[idx] = __float2half(hn);
}

// ================= standalone attention (decoder t=0 only) =================
__global__ void attention_k(const __half* __restrict__ allh16, const __half* __restrict__ allhz16,
                            const __half* __restrict__ hprev16, const float* __restrict__ cvec,
                            __half* __restrict__ hcat16) {
    int b = blockIdx.x;
    int tid = threadIdx.x, lane = tid & 31, w = tid >> 5;
    __shared__ float sc[21];
    __shared__ float wts[21];
    const float* cb = cvec + (size_t)b * HH;

    // pass 1: vectorized 16B fp16 loads + 2x16B f32 query loads
    for (int s = w; s < 21; s += 8) {
        const __half* hs = (s < TIN)  ? (allh16 + ((size_t)s * BB + b) * HH)
                         : (s == TIN) ? (hprev16 + (size_t)b * HH)
                                      : (allhz16 + ((size_t)(s - TIN - 1) * BB + b) * HH);
        float part = 0.f;
        for (int q = lane; q < 128; q += 32)
            part += dot8(((const float4*)hs)[q], ((const float4*)cb)[2 * q], ((const float4*)cb)[2 * q + 1]);
#pragma unroll
        for (int off = 16; off; off >>= 1) part += __shfl_down_sync(0xffffffffu, part, off);
        if (lane == 0) sc[s] = part;
    }
    __syncthreads();
    if (tid == 0) {
        float mx = sc[0];
        for (int s = 1; s < 21; s++) mx = fmaxf(mx, sc[s]);
        float sum = 0.f;
        for (int s = 0; s < 21; s++) { float e = expf(sc[s] - mx); wts[s] = e; sum += e; }
        float inv = 1.f / sum;
        for (int s = 0; s < 21; s++) wts[s] *= inv;
    }
    __syncthreads();
    __half* out = hcat16 + (size_t)b * 2048;
    const __half* hp = hprev16 + (size_t)b * HH;
    for (int u = tid; u < HH; u += blockDim.x) {
        float accv = 0.f;
#pragma unroll
        for (int s = 0; s < 21; s++) {
            const __half* hs = (s < TIN)  ? (allh16 + ((size_t)s * BB + b) * HH)
                             : (s == TIN) ? hp
                                          : (allhz16 + ((size_t)(s - TIN - 1) * BB + b) * HH);
            accv += wts[s] * __half2float(hs[u]);
        }
        out[u] = __float2half(accv);
        out[HH + u] = hp[u];
    }
}

// ================= fused decoder cell(t) + attention(t+1), one block per batch row =================
__global__ void cellatt_k(const float* __restrict__ gates, const float* __restrict__ bias,
                          const float* __restrict__ cprev,
                          float* __restrict__ cout, float* __restrict__ houtf,
                          __half* __restrict__ hout16,
                          const __half* __restrict__ allh16, const __half* __restrict__ allhz16,
                          __half* __restrict__ hcat16) {
    __shared__ __align__(16) float cs[1024];        // fresh c (attention query)
    __shared__ __align__(16) __half hs16[1024];     // fresh h (TIN state)
    __shared__ float sc[21];
    __shared__ float wts[21];
    int b = blockIdx.x;
    int tid = threadIdx.x, lane = tid & 31, w = tid >> 5;

    // ---- LSTM cell for this batch row ----
    const float* g = gates + (size_t)b * GG;
#pragma unroll
    for (int i = 0; i < 4; i++) {
        int u = tid + 256 * i;
        float gi = g[u] + bias[u];
        float gf = g[HH + u] + bias[HH + u];
        float gc = g[2 * HH + u] + bias[2 * HH + u];
        float go = g[3 * HH + u] + bias[3 * HH + u];
        float c = cprev[(size_t)b * HH + u];
        float si = sigma(gi), sf = sigma(gf), so = sigma(go);
        float cn = sf * c + si * tanha(gc);
        float hn = so * tanha(cn);
        cout[(size_t)b * HH + u] = cn;
        houtf[(size_t)b * HH + u] = hn;
        __half hh = __float2half(hn);
        hout16[(size_t)b * HH + u] = hh;
        cs[u] = cn;
        hs16[u] = hh;
    }
    __syncthreads();

    // ---- attention pass 1 (query = fresh c from smem), vectorized ----
    for (int s = w; s < 21; s += 8) {
        float part = 0.f;
        const __half* hs = (s == TIN) ? hs16
                         : (s < TIN)  ? (allh16 + ((size_t)s * BB + b) * HH)
                                      : (allhz16 + ((size_t)(s - TIN - 1) * BB + b) * HH);
        for (int q = lane; q < 128; q += 32)
            part += dot8(((const float4*)hs)[q], ((const float4*)cs)[2 * q], ((const float4*)cs)[2 * q + 1]);
#pragma unroll
        for (int off = 16; off; off >>= 1) part += __shfl_down_sync(0xffffffffu, part, off);
        if (lane == 0) sc[s] = part;
    }
    __syncthreads();
    if (tid == 0) {
        float mx = sc[0];
        for (int s = 1; s < 21; s++) mx = fmaxf(mx, sc[s]);
        float sum = 0.f;
        for (int s = 0; s < 21; s++) { float e = expf(sc[s] - mx); wts[s] = e; sum += e; }
        float inv = 1.f / sum;
        for (int s = 0; s < 21; s++) wts[s] *= inv;
    }
    __syncthreads();
    __half* out = hcat16 + (size_t)b * 2048;
    for (int u = tid; u < HH; u += 256) {
        float accv = wts[TIN] * __half2float(hs16[u]);
#pragma unroll
        for (int s = 0; s < TIN; s++)
            accv += wts[s] * __half2float(allh16[((size_t)s * BB + b) * HH + u]);
#pragma unroll
        for (int s = TIN + 1; s < 21; s++)
            accv += wts[s] * __half2float(allhz16[((size_t)(s - TIN - 1) * BB + b) * HH + u]);
        out[u] = __float2half(accv);
        out[HH + u] = hs16[u];
    }
}

// ================= small setup kernels =================
__global__ void prep_bias2_k(const float* wihA, const float* vecA, const float* b1A, const float* b2A, float* outA,
                             const float* wihB, const float* vecB, const float* b1B, const float* b2B, float* outB) {
    const float* wih = blockIdx.y ? wihB : wihA;
    const float* vec = blockIdx.y ? vecB : vecA;
    const float* b1  = blockIdx.y ? b1B  : b1A;
    const float* b2  = blockIdx.y ? b2B  : b2A;
    float* out       = blockIdx.y ? outB : outA;
    int wid = (blockIdx.x * blockDim.x + threadIdx.x) >> 5;
    int lane = threadIdx.x & 31;
    if (wid >= GG) return;
    const float* row = wih + (size_t)wid * DD;
    float s = 0.f;
    for (int d = lane; d < DD; d += 32) s += row[d] * vec[d];
#pragma unroll
    for (int off = 16; off; off >>= 1) s += __shfl_down_sync(0xffffffffu, s, off);
    if (lane == 0) out[wid] = b1[wid] + b2[wid] + s;
}

__global__ void f2h2_k(const float* __restrict__ s0, __half* __restrict__ d0,
                       const float* __restrict__ s1, __half* __restrict__ d1, int n) {
    int i = blockIdx.x * blockDim.x + threadIdx.x;
    const float* s = blockIdx.y ? s1 : s0;
    __half* d = blockIdx.y ? d1 : d0;
    if (i < n) d[i] = __float2half(s[i]);
}

__global__ void pack_wcat16_k(const float* __restrict__ whh, const float* __restrict__ weff) {
    size_t idx = (size_t)blockIdx.x * blockDim.x + threadIdx.x;
    if (idx >= (size_t)GG * 2048) return;
    int j = (int)(idx >> 11), m = (int)(idx & 2047);
    float v = (m < 1024) ? whh[(size_t)j * 1024 + m] : weff[(size_t)j * 1024 + (m - 1024)];
    d_Wcat16[idx] = __float2half(v);
}

__global__ void pose_fin_k(const float* __restrict__ pc, const float* __restrict__ pb,
                           float* __restrict__ out) {
    int idx = blockIdx.x * blockDim.x + threadIdx.x;
    if (idx >= BB * TOUT * PP) return;
    int pp = idx % PP;
    int bt = idx / PP;
    int t = bt % TOUT, b = bt / TOUT;
    out[idx] = pc[((size_t)t * BB + b) * 256 + pp] + pb[pp];
}

// ================= host orchestration =================
extern "C" void kernel_launch(void* const* d_in, const int* in_sizes, int n_in,
                              void* d_out, int out_size) {
    const float* x        = (const float*)d_in[0];
    const float* z        = (const float*)d_in[1];
    const float* wf       = (const float*)d_in[2];
    const float* bf       = (const float*)d_in[3];
    const float* enc_wih  = (const float*)d_in[4];
    const float* enc_whh  = (const float*)d_in[5];
    const float* enc_bih  = (const float*)d_in[6];
    const float* enc_bhh  = (const float*)d_in[7];
    const float* encp_wih = (const float*)d_in[8];
    const float* encp_whh = (const float*)d_in[9];
    const float* encp_bih = (const float*)d_in[10];
    const float* encp_bhh = (const float*)d_in[11];
    const float* dec_wih  = (const float*)d_in[12];
    const float* dec_whh  = (const float*)d_in[13];
    const float* dec_bih  = (const float*)d_in[14];
    const float* dec_bhh  = (const float*)d_in[15];
    const float* lin_w    = (const float*)d_in[16];
    const float* lin_b    = (const float*)d_in[17];
    const float* pose_w   = (const float*)d_in[18];
    const float* pose_b   = (const float*)d_in[19];
    float* out = (float*)d_out;

    void* pv;
    cudaGetSymbolAddress(&pv, d_WcombX);  float* WcombX  = (float*)pv;
    cudaGetSymbolAddress(&pv, d_WcombZ);  float* WcombZ  = (float*)pv;
    cudaGetSymbolAddress(&pv, d_bcombX);  float* bcombX  = (float*)pv;
    cudaGetSymbolAddress(&pv, d_bcombZ);  float* bcombZ  = (float*)pv;
    cudaGetSymbolAddress(&pv, d_WeffF);   float* WeffF   = (float*)pv;
    cudaGetSymbolAddress(&pv, d_Wcat16);  __half* Wcat16 = (__half*)pv;
    cudaGetSymbolAddress(&pv, d_whhX16);  __half* whhX16 = (__half*)pv;
    cudaGetSymbolAddress(&pv, d_whhZ16);  __half* whhZ16 = (__half*)pv;
    cudaGetSymbolAddress(&pv, d_bcat);    float* bcat    = (float*)pv;
    cudaGetSymbolAddress(&pv, d_ginX);    float* ginX    = (float*)pv;
    cudaGetSymbolAddress(&pv, d_ginZ);    float* ginZ    = (float*)pv;
    cudaGetSymbolAddress(&pv, d_allh16X); __half* allh16X = (__half*)pv;
    cudaGetSymbolAddress(&pv, d_allh16Z); __half* allh16Z = (__half*)pv;
    cudaGetSymbolAddress(&pv, d_cX);      float* cX      = (float*)pv;
    cudaGetSymbolAddress(&pv, d_cZ);      float* cZ      = (float*)pv;
    cudaGetSymbolAddress(&pv, d_decc);    float* decc    = (float*)pv;
    cudaGetSymbolAddress(&pv, d_gates);   float* gates   = (float*)pv;
    cudaGetSymbolAddress(&pv, d_hcat16);  __half* hcat16 = (__half*)pv;
    cudaGetSymbolAddress(&pv, d_dechs);   float* dechs   = (float*)pv;
    cudaGetSymbolAddress(&pv, d_dechs16); __half* dechs16 = (__half*)pv;
    cudaGetSymbolAddress(&pv, d_poseC);   float* poseC   = (float*)pv;

    cudaFuncSetAttribute(hgemm_k<A_PLAIN, B_KN, true, false>, cudaFuncAttributeMaxDynamicSharedMemorySize, SMEM_KN_BYTES);
    cudaFuncSetAttribute(hgemm_k<A_XG,    B_NK, false, true>, cudaFuncAttributeMaxDynamicSharedMemorySize, SMEM_NK_BYTES);
    cudaFuncSetAttribute(hgemm_k<A_PLAIN, B_KN, true, true>,  cudaFuncAttributeMaxDynamicSharedMemorySize, SMEM_KN_BYTES);
    cudaFuncSetAttribute(hgemm_k<A_PLAIN, B_NK, true, true>,  cudaFuncAttributeMaxDynamicSharedMemorySize, SMEM_NK_BYTES);
    cudaFuncSetAttribute(hgemm16_k, cudaFuncAttributeMaxDynamicSharedMemorySize, H_SMEM_BYTES);

    // ---- Wcomb = enc_wih @ wf (tf32, both encoders) ----
    {
        GP p0 = {enc_wih,  wf, WcombX, GG, PP, DD, DD, PP, 256};
        GP p1 = {encp_wih, wf, WcombZ, GG, PP, DD, DD, PP, 256};
        hgemm_k<A_PLAIN, B_KN, true, false><<<dim3(GG / 128, 1, 2), 256, SMEM_KN_BYTES>>>(p0, p1);
    }
    // ---- gin = x @ Wcomb^T (tf32, both encoders) ----
    {
        GP p0 = {x, WcombX, ginX, TIN * BB, GG, PP, PP, 256, GG};
        GP p1 = {z, WcombZ, ginZ, TIN * BB, GG, PP, PP, 256, GG};
        hgemm_k<A_XG, B_NK, false, true><<<dim3(TIN * BB / 128, GG / 128, 2), 256, SMEM_NK_BYTES>>>(p0, p1);
    }
    // ---- whh -> fp16 (both encoders, one launch) ----
    f2h2_k<<<dim3((GG * HH + 255) / 256, 2), 256>>>(enc_whh, whhX16, encp_whh, whhZ16, GG * HH);
    // ---- folded biases (both encoders, one launch) ----
    prep_bias2_k<<<dim3(512, 2), 256>>>(enc_wih, bf, enc_bih, enc_bhh, bcombX,
                                        encp_wih, bf, encp_bih, encp_bhh, bcombZ);

    // ---- encoder t=0 ----
    {
        CP pa = {ginX, nullptr, bcombX, nullptr, cX, nullptr, allh16X};
        CP pb = {ginZ, nullptr, bcombZ, nullptr, cZ, nullptr, allh16Z};
        lstm_cell_k<<<dim3(4096, 2), 256>>>(pa, pb, 1);
    }
    // ---- encoder recurrence (fp16 GEMM) ----
    for (int t = 1; t < TIN; t++) {
        GP16 p0 = {allh16X + (size_t)(t - 1) * BB * HH, whhX16, gates,                   BB, GG, HH, HH, HH, GG};
        GP16 p1 = {allh16Z + (size_t)(t - 1) * BB * HH, whhZ16, gates + (size_t)BB * GG, BB, GG, HH, HH, HH, GG};
        hgemm16_k<<<dim3(BB / 128, GG / 128, 2), 256, H_SMEM_BYTES>>>(p0, p1);
        CP pa = {gates,                   ginX + (size_t)t * BB * GG, bcombX, cX, cX, nullptr, allh16X + (size_t)t * BB * HH};
        CP pb = {gates + (size_t)BB * GG, ginZ + (size_t)t * BB * GG, bcombZ, cZ, cZ, nullptr, allh16Z + (size_t)t * BB * HH};
        lstm_cell_k<<<dim3(4096, 2), 256>>>(pa, pb, 0);
    }

    // ---- decoder setup ----
    {   // Weff = dec_wih @ lin_w (tf32, f32 out)
        GP p0 = {dec_wih, lin_w, WeffF, GG, HH, DD, DD, HH, HH};
        hgemm_k<A_PLAIN, B_KN, true, true><<<dim3(GG / 128, HH / 128, 1), 256, SMEM_KN_BYTES>>>(p0, p0);
    }
    pack_wcat16_k<<<(int)(((size_t)GG * 2048 + 255) / 256), 256>>>(dec_whh, WeffF);
    prep_bias2_k<<<dim3(512, 1), 256>>>(dec_wih, lin_b, dec_bih, dec_bhh, bcat,
                                        dec_wih, lin_b, dec_bih, dec_bhh, bcat);

    // ---- decoder: attention(0) standalone, then GEMM + fused(cell+next attention) ----
    attention_k<<<BB, 256>>>(allh16X, allh16Z,
                             allh16X + (size_t)(TIN - 1) * BB * HH, cX, hcat16);
    for (int t = 0; t < TOUT; t++) {
        GP16 p0 = {hcat16, Wcat16, gates, BB, GG, 2048, 2048, 2048, GG};
        hgemm16_k<<<dim3(BB / 128, GG / 128, 1), 256, H_SMEM_BYTES>>>(p0, p0);
        const float* cptr = (t == 0) ? cX : decc;
        if (t < TOUT - 1) {
            cellatt_k<<<BB, 256>>>(gates, bcat, cptr, decc,
                                   dechs + (size_t)t * BB * HH, dechs16 + (size_t)t * BB * HH,
                                   allh16X, allh16Z, hcat16);
        } else {
            CP pa = {gates, nullptr, bcat, cptr, decc,
                     dechs + (size_t)t * BB * HH, dechs16 + (size_t)t * BB * HH};
            lstm_cell_k<<<dim3(4096, 1), 256>>>(pa, pa, 0);
        }
    }

    // ---- output projection (tf32) + epilogue ----
    {
        GP p0 = {dechs, pose_w, poseC, TOUT * BB, PP, HH, HH, HH, 256};
        hgemm_k<A_PLAIN, B_NK, true, true><<<dim3(TOUT * BB / 128, 1, 1), 256, SMEM_NK_BYTES>>>(p0, p0);
        pose_fin_k<<<(BB * TOUT * PP + 255) / 256, 256>>>(poseC, pose_b, out);
    }
}

// round 17
// speedup vs baseline: 1.4607x; 1.0428x over previous
#include <cuda_runtime.h>
#include <cuda_fp16.h>
#include <mma.h>
#include <math.h>

using namespace nvcuda;

#define BB 1024
#define HH 1024
#define DD 512
#define PP 66
#define TIN 10
#define TOUT 25
#define GG 4096   // 4*HH

// ---------------- static device scratch (no allocations allowed) ----------------
__device__ float d_WcombX[(size_t)GG * 256];
__device__ float d_WcombZ[(size_t)GG * 256];
__device__ float d_bcombX[GG];
__device__ float d_bcombZ[GG];
__device__ float d_WeffF[(size_t)GG * HH];             // dec_wih @ lin_w, f32
__device__ __half d_Wcat16[(size_t)GG * 2048];         // fp16: [dec_whh | Weff]
__device__ __half d_whhX16[(size_t)GG * HH];
__device__ __half d_whhZ16[(size_t)GG * HH];
__device__ float d_bcat[GG];
__device__ float d_ginX[(size_t)TIN * BB * GG];
__device__ float d_ginZ[(size_t)TIN * BB * GG];
__device__ __half d_allh16X[(size_t)TIN * BB * HH];
__device__ __half d_allh16Z[(size_t)TIN * BB * HH];
__device__ float d_cX[BB * HH];
__device__ float d_cZ[BB * HH];
__device__ float d_decc[BB * HH];
__device__ float d_gates[(size_t)2 * BB * GG];
__device__ __half d_hcat16[(size_t)BB * 2048];         // [atth | h_n] fp16
__device__ float d_dechs[(size_t)TOUT * BB * HH];      // f32 (pose GEMM input)
__device__ __half d_dechs16[(size_t)TOUT * BB * HH];   // fp16 (attention input)
__device__ float d_poseC[(size_t)TOUT * BB * 256];

// ================= helpers =================
__device__ __forceinline__ unsigned sptr(const void* p) {
    return (unsigned)__cvta_generic_to_shared(p);
}
__device__ __forceinline__ void cpa16(unsigned d, const void* s, bool pr) {
    int sz = pr ? 16 : 0;
    asm volatile("cp.async.cg.shared.global [%0], [%1], 16, %2;\n" :: "r"(d), "l"(s), "r"(sz));
}
__device__ __forceinline__ void cpa16u(unsigned d, const void* s) {
    asm volatile("cp.async.cg.shared.global [%0], [%1], 16;\n" :: "r"(d), "l"(s));
}
__device__ __forceinline__ void cpa4(unsigned d, const void* s, bool pr) {
    int sz = pr ? 4 : 0;
    asm volatile("cp.async.ca.shared.global [%0], [%1], 4, %2;\n" :: "r"(d), "l"(s), "r"(sz));
}
__device__ __forceinline__ float tanha(float x) {
    float y;
    asm("tanh.approx.f32 %0, %1;" : "=f"(y) : "f"(x));
    return y;
}
__device__ __forceinline__ float sigma(float x) {
    return 0.5f + 0.5f * tanha(0.5f * x);
}
// dot of 8 fp16 (one float4 worth) with 8 f32 (two float4)
__device__ __forceinline__ float dot8(float4 hv, float4 c0, float4 c1) {
    const __half2* h2 = (const __half2*)&hv;
    float2 a0 = __half22float2(h2[0]);
    float2 a1 = __half22float2(h2[1]);
    float2 a2 = __half22float2(h2[2]);
    float2 a3 = __half22float2(h2[3]);
    return a0.x * c0.x + a0.y * c0.y + a1.x * c0.z + a1.y * c0.w
         + a2.x * c1.x + a2.y * c1.y + a3.x * c1.z + a3.y * c1.w;
}

// ================= fp16 recurrent GEMM: 128x128 block, 64x32 warp tile, k-chunk 64 =================
struct GP16 {
    const __half* A;     // [M, K] row-major
    const __half* Bm;    // [N, K] row-major (weights)
    float* C;            // [M, N]
    int M, N, K, lda, ldb, ldc;
};

#define H_LD 72                          // halfs per smem row (64 + 8 pad)
#define H_TILE (128 * H_LD)
#define H_STAGE (2 * H_TILE)
#define H_NSTAGE 3
#define H_SMEM_BYTES (H_NSTAGE * H_STAGE * 2)   // 110592 B

__global__ __launch_bounds__(256, 2) void hgemm16_k(GP16 p0, GP16 p1) {
    extern __shared__ __half smh[];
    GP16 p = (blockIdx.z == 0) ? p0 : p1;
    const int tid = threadIdx.x;
    const int warp = tid >> 5;
    const int wm = warp & 1;             // 2 x 4 warp grid, warp tile 64m x 32n
    const int wn = warp >> 1;
    const int m0 = blockIdx.x * 128, n0 = blockIdx.y * 128;
    const int KT = p.K >> 6;             // 64-k chunks

    wmma::fragment<wmma::accumulator, 16, 16, 16, float> acc[4][2];
#pragma unroll
    for (int i = 0; i < 4; i++)
#pragma unroll
        for (int j = 0; j < 2; j++) wmma::fill_fragment(acc[i][j], 0.f);

    auto loadChunk = [&](int kt, int stg) {
        __half* As = smh + stg * H_STAGE;
        __half* Bs = As + H_TILE;
        const int k0 = kt << 6;
#pragma unroll
        for (int i = 0; i < 4; i++) {
            int q = tid + 256 * i;
            int r = q >> 3, u = q & 7;
            cpa16u(sptr(As + r * H_LD + u * 8), p.A + (size_t)(m0 + r) * p.lda + k0 + u * 8);
        }
#pragma unroll
        for (int i = 0; i < 4; i++) {
            int q = tid + 256 * i;
            int r = q >> 3, u = q & 7;
            cpa16u(sptr(Bs + r * H_LD + u * 8), p.Bm + (size_t)(n0 + r) * p.ldb + k0 + u * 8);
        }
    };

    loadChunk(0, 0);
    asm volatile("cp.async.commit_group;\n");
    if (KT > 1) loadChunk(1, 1);
    asm volatile("cp.async.commit_group;\n");

    for (int kt = 0; kt < KT; kt++) {
        if (kt < KT - 1) { asm volatile("cp.async.wait_group 1;\n"); }
        else             { asm volatile("cp.async.wait_group 0;\n"); }
        __syncthreads();
        if (kt + 2 < KT) {
            loadChunk(kt + 2, (kt + 2) % H_NSTAGE);
            asm volatile("cp.async.commit_group;\n");
        }
        const int stg = kt % H_NSTAGE;
        __half* As = smh + stg * H_STAGE;
        __half* Bs = As + H_TILE;
#pragma unroll
        for (int kk = 0; kk < 4; kk++) {
            wmma::fragment<wmma::matrix_a, 16, 16, 16, __half, wmma::row_major> af[4];
#pragma unroll
            for (int i = 0; i < 4; i++)
                wmma::load_matrix_sync(af[i], As + (wm * 64 + i * 16) * H_LD + kk * 16, H_LD);
            wmma::fragment<wmma::matrix_b, 16, 16, 16, __half, wmma::col_major> bf[2];
#pragma unroll
            for (int j = 0; j < 2; j++)
                wmma::load_matrix_sync(bf[j], Bs + (wn * 32 + j * 16) * H_LD + kk * 16, H_LD);
#pragma unroll
            for (int i = 0; i < 4; i++)
#pragma unroll
                for (int j = 0; j < 2; j++)
                    wmma::mma_sync(acc[i][j], af[i], bf[j], acc[i][j]);
        }
    }

#pragma unroll
    for (int i = 0; i < 4; i++)
#pragma unroll
        for (int j = 0; j < 2; j++)
            wmma::store_matrix_sync(p.C + (size_t)(m0 + wm * 64 + i * 16) * p.ldc + n0 + wn * 32 + j * 16,
                                    acc[i][j], p.ldc, wmma::mem_row_major);
}

// ================= tf32 GEMM (setup + pose only) =================
struct GP {
    const float* A;
    const float* Bm;
    float* C;
    int M, N, K, lda, ldb, ldc;
};
enum { A_PLAIN = 0, A_XG = 1 };
enum { B_NK = 0, B_KN = 1 };

#define ST_A 4608
#define ST_B_NK 4608
#define ST_B_KN 4224
#define NSTAGE 3
#define SMEM_NK_BYTES (NSTAGE * (ST_A + ST_B_NK) * 4)
#define SMEM_KN_BYTES (NSTAGE * (ST_A + ST_B_KN) * 4)

template <int AMAP, int BMODE, bool ALA, bool ALB>
__global__ __launch_bounds__(256, 2) void hgemm_k(GP p0, GP p1) {
    constexpr int STB = (BMODE == B_NK) ? ST_B_NK : ST_B_KN;
    constexpr int STST = ST_A + STB;
    extern __shared__ float sm[];
    GP p = (blockIdx.z == 0) ? p0 : p1;
    const int tid = threadIdx.x;
    const int warp = tid >> 5;
    const int wm = warp & 1;
    const int wn = warp >> 1;
    const int m0 = blockIdx.x * 128, n0 = blockIdx.y * 128;
    const int KT = (p.K + 31) >> 5;

    wmma::fragment<wmma::accumulator, 16, 16, 8, float> acc[4][2];
#pragma unroll
    for (int i = 0; i < 4; i++)
#pragma unroll
        for (int j = 0; j < 2; j++) wmma::fill_fragment(acc[i][j], 0.f);

    auto loadTile = [&](int kt, int stg) {
        float* As = sm + stg * STST;
        float* Bs = As + ST_A;
        const int k0 = kt << 5;
        if (ALA) {
#pragma unroll
            for (int i = 0; i < 4; i++) {
                int c = tid + 256 * i;
                int m = c >> 3, kq = c & 7;
                int gm = m0 + m, gk = k0 + kq * 4;
                bool pr = (gm < p.M) && (gk < p.K);
                const float* src = pr ? (p.A + (size_t)gm * p.lda + gk) : p.A;
                cpa16(sptr(As + m * 36 + kq * 4), src, pr);
            }
        } else {
#pragma unroll
            for (int i = 0; i < 16; i++) {
                int idx = tid + 256 * i;
                int m = idx >> 5, k = idx & 31;
                int gm = m0 + m, gk = k0 + k;
                bool pr = (gm < p.M) && (gk < p.K);
                const float* src = p.A;
                if (pr) {
                    size_t off;
                    if (AMAP == A_XG) { int t = gm / BB, b = gm % BB; off = (size_t)b * (TIN * PP) + (size_t)t * PP + gk; }
                    else off = (size_t)gm * p.lda + gk;
                    src = p.A + off;
                }
                cpa4(sptr(As + m * 36 + k), src, pr);
            }
        }
        if (BMODE == B_NK) {
            if (ALB) {
#pragma unroll
                for (int i = 0; i < 4; i++) {
                    int c = tid + 256 * i;
                    int n = c >> 3, kq = c & 7;
                    int gn = n0 + n, gk = k0 + kq * 4;
                    bool pr = (gn < p.N) && (gk < p.K);
                    const float* src = pr ? (p.Bm + (size_t)gn * p.ldb + gk) : p.Bm;
                    cpa16(sptr(Bs + n * 36 + kq * 4), src, pr);
                }
            } else {
#pragma unroll
                for (int i = 0; i < 16; i++) {
                    int idx = tid + 256 * i;
                    int n = idx >> 5, k = idx & 31;
                    int gn = n0 + n, gk = k0 + k;
                    bool pr = (gn < p.N) && (gk < p.K);
                    const float* src = pr ? (p.Bm + (size_t)gn * p.ldb + gk) : p.Bm;
                    cpa4(sptr(Bs + n * 36 + k), src, pr);
                }
            }
        } else {
            if (ALB) {
#pragma unroll
                for (int i = 0; i < 4; i++) {
                    int c = tid + 256 * i;
                    int k = c >> 5, nq = c & 31;
                    int gk = k0 + k, gn = n0 + nq * 4;
                    bool pr = (gk < p.K) && (gn < p.N);
                    const float* src = pr ? (p.Bm + (size_t)gk * p.ldb + gn) : p.Bm;
                    cpa16(sptr(Bs + k * 132 + nq * 4), src, pr);
                }
            } else {
#pragma unroll
                for (int i = 0; i < 16; i++) {
                    int idx = tid + 256 * i;
                    int k = idx >> 7, n = idx & 127;
                    int gk = k0 + k, gn = n0 + n;
                    bool pr = (gk < p.K) && (gn < p.N);
                    const float* src = pr ? (p.Bm + (size_t)gk * p.ldb + gn) : p.Bm;
                    cpa4(sptr(Bs + k * 132 + n), src, pr);
                }
            }
        }
    };

    loadTile(0, 0);
    asm volatile("cp.async.commit_group;\n");
    if (KT > 1) loadTile(1, 1);
    asm volatile("cp.async.commit_group;\n");

    for (int kt = 0; kt < KT; kt++) {
        if (kt < KT - 1) { asm volatile("cp.async.wait_group 1;\n"); }
        else             { asm volatile("cp.async.wait_group 0;\n"); }
        __syncthreads();
        if (kt + 2 < KT) {
            loadTile(kt + 2, (kt + 2) % NSTAGE);
            asm volatile("cp.async.commit_group;\n");
        }
        const int stg = kt % NSTAGE;
        float* As = sm + stg * STST;
        float* Bs = As + ST_A;
#pragma unroll
        for (int kk = 0; kk < 4; kk++) {
            wmma::fragment<wmma::matrix_a, 16, 16, 8, wmma::precision::tf32, wmma::row_major> af[4];
#pragma unroll
            for (int i = 0; i < 4; i++)
                wmma::load_matrix_sync(af[i], As + (wm * 64 + i * 16) * 36 + kk * 8, 36);
            if (BMODE == B_NK) {
                wmma::fragment<wmma::matrix_b, 16, 16, 8, wmma::precision::tf32, wmma::col_major> bf[2];
#pragma unroll
                for (int j = 0; j < 2; j++)
                    wmma::load_matrix_sync(bf[j], Bs + (wn * 32 + j * 16) * 36 + kk * 8, 36);
#pragma unroll
                for (int i = 0; i < 4; i++)
#pragma unroll
                    for (int j = 0; j < 2; j++)
                        wmma::mma_sync(acc[i][j], af[i], bf[j], acc[i][j]);
            } else {
                wmma::fragment<wmma::matrix_b, 16, 16, 8, wmma::precision::tf32, wmma::row_major> bf[2];
#pragma unroll
                for (int j = 0; j < 2; j++)
                    wmma::load_matrix_sync(bf[j], Bs + (kk * 8) * 132 + wn * 32 + j * 16, 132);
#pragma unroll
                for (int i = 0; i < 4; i++)
#pragma unroll
                    for (int j = 0; j < 2; j++)
                        wmma::mma_sync(acc[i][j], af[i], bf[j], acc[i][j]);
            }
        }
    }

#pragma unroll
    for (int i = 0; i < 4; i++)
#pragma unroll
        for (int j = 0; j < 2; j++)
            wmma::store_matrix_sync(p.C + (size_t)(m0 + wm * 64 + i * 16) * p.ldc + n0 + wn * 32 + j * 16,
                                    acc[i][j], p.ldc, wmma::mem_row_major);
}

// ================= LSTM pointwise cell (fast transcendentals) =================
struct CP {
    const float* mm;
    const float* pre;
    const float* bias;
    const float* cprev;
    float* cout;
    float* hout;         // optional f32 h
    __half* hout16;      // optional fp16 h
};

__global__ void lstm_cell_k(CP pa, CP pb, int first) {
    CP p = blockIdx.y ? pb : pa;
    int idx = blockIdx.x * blockDim.x + threadIdx.x;
    if (idx >= BB * HH) return;
    int b = idx >> 10, u = idx & 1023;
    const float* g = p.mm + (size_t)b * GG;
    float gi = g[u], gf = g[HH + u], gc = g[2 * HH + u], go = g[3 * HH + u];
    if (p.pre) {
        const float* q = p.pre + (size_t)b * GG;
        gi += q[u]; gf += q[HH + u]; gc += q[2 * HH + u]; go += q[3 * HH + u];
    }
    if (p.bias) {
        gi += p.bias[u]; gf += p.bias[HH + u]; gc += p.bias[2 * HH + u]; go += p.bias[3 * HH + u];
    }
    float c = first ? 0.f : p.cprev[idx];
    float si = sigma(gi);
    float sf = sigma(gf);
    float so = sigma(go);
    float cn = sf * c + si * tanha(gc);
    float hn = so * tanha(cn);
    p.cout[idx] = cn;
    if (p.hout) p.hout[idx] = hn;
    if (p.hout16) p.hout16[idx] = __float2half(hn);
}

// ================= standalone attention (decoder t=0 only) =================
__global__ void attention_k(const __half* __restrict__ allh16, const __half* __restrict__ allhz16,
                            const __half* __restrict__ hprev16, const float* __restrict__ cvec,
                            __half* __restrict__ hcat16) {
    int b = blockIdx.x;
    int tid = threadIdx.x, lane = tid & 31, w = tid >> 5;
    __shared__ float sc[21];
    __shared__ float wts[21];
    const float* cb = cvec + (size_t)b * HH;

    // pass 1: vectorized 16B fp16 loads + 2x16B f32 query loads
    for (int s = w; s < 21; s += 8) {
        const __half* hs = (s < TIN)  ? (allh16 + ((size_t)s * BB + b) * HH)
                         : (s == TIN) ? (hprev16 + (size_t)b * HH)
                                      : (allhz16 + ((size_t)(s - TIN - 1) * BB + b) * HH);
        float part = 0.f;
        for (int q = lane; q < 128; q += 32)
            part += dot8(((const float4*)hs)[q], ((const float4*)cb)[2 * q], ((const float4*)cb)[2 * q + 1]);
#pragma unroll
        for (int off = 16; off; off >>= 1) part += __shfl_down_sync(0xffffffffu, part, off);
        if (lane == 0) sc[s] = part;
    }
    __syncthreads();
    if (tid == 0) {
        float mx = sc[0];
        for (int s = 1; s < 21; s++) mx = fmaxf(mx, sc[s]);
        float sum = 0.f;
        for (int s = 0; s < 21; s++) { float e = expf(sc[s] - mx); wts[s] = e; sum += e; }
        float inv = 1.f / sum;
        for (int s = 0; s < 21; s++) wts[s] *= inv;
    }
    __syncthreads();
    // pass 2: vectorized — 256 threads x 4 halfs (float2 loads, half2 stores)
    __half* out = hcat16 + (size_t)b * 2048;
    const __half* hp = hprev16 + (size_t)b * HH;
    {
        int q = tid;
        float a0 = 0.f, a1 = 0.f, a2 = 0.f, a3 = 0.f;
#pragma unroll
        for (int s = 0; s < 21; s++) {
            const __half* hs = (s < TIN)  ? (allh16 + ((size_t)s * BB + b) * HH)
                             : (s == TIN) ? hp
                                          : (allhz16 + ((size_t)(s - TIN - 1) * BB + b) * HH);
            float2 hv = ((const float2*)hs)[q];
            const __half2* h2 = (const __half2*)&hv;
            float2 x0 = __half22float2(h2[0]), x1 = __half22float2(h2[1]);
            float wv = wts[s];
            a0 += wv * x0.x; a1 += wv * x0.y; a2 += wv * x1.x; a3 += wv * x1.y;
        }
        ((__half2*)out)[2 * q] = __floats2half2_rn(a0, a1);
        ((__half2*)out)[2 * q + 1] = __floats2half2_rn(a2, a3);
        ((float2*)(out + HH))[q] = ((const float2*)hp)[q];
    }
}

// ================= fused decoder cell(t) + attention(t+1), one block per batch row =================
__global__ void cellatt_k(const float* __restrict__ gates, const float* __restrict__ bias,
                          const float* __restrict__ cprev,
                          float* __restrict__ cout, float* __restrict__ houtf,
                          __half* __restrict__ hout16,
                          const __half* __restrict__ allh16, const __half* __restrict__ allhz16,
                          __half* __restrict__ hcat16) {
    __shared__ __align__(16) float cs[1024];        // fresh c (attention query)
    __shared__ __align__(16) __half hs16[1024];     // fresh h (TIN state)
    __shared__ float sc[21];
    __shared__ float wts[21];
    int b = blockIdx.x;
    int tid = threadIdx.x, lane = tid & 31, w = tid >> 5;

    // ---- LSTM cell for this batch row ----
    const float* g = gates + (size_t)b * GG;
#pragma unroll
    for (int i = 0; i < 4; i++) {
        int u = tid + 256 * i;
        float gi = g[u] + bias[u];
        float gf = g[HH + u] + bias[HH + u];
        float gc = g[2 * HH + u] + bias[2 * HH + u];
        float go = g[3 * HH + u] + bias[3 * HH + u];
        float c = cprev[(size_t)b * HH + u];
        float si = sigma(gi), sf = sigma(gf), so = sigma(go);
        float cn = sf * c + si * tanha(gc);
        float hn = so * tanha(cn);
        cout[(size_t)b * HH + u] = cn;
        houtf[(size_t)b * HH + u] = hn;
        __half hh = __float2half(hn);
        hout16[(size_t)b * HH + u] = hh;
        cs[u] = cn;
        hs16[u] = hh;
    }
    __syncthreads();

    // ---- attention pass 1 (query = fresh c from smem), vectorized ----
    for (int s = w; s < 21; s += 8) {
        float part = 0.f;
        const __half* hs = (s == TIN) ? hs16
                         : (s < TIN)  ? (allh16 + ((size_t)s * BB + b) * HH)
                                      : (allhz16 + ((size_t)(s - TIN - 1) * BB + b) * HH);
        for (int q = lane; q < 128; q += 32)
            part += dot8(((const float4*)hs)[q], ((const float4*)cs)[2 * q], ((const float4*)cs)[2 * q + 1]);
#pragma unroll
        for (int off = 16; off; off >>= 1) part += __shfl_down_sync(0xffffffffu, part, off);
        if (lane == 0) sc[s] = part;
    }
    __syncthreads();
    if (tid == 0) {
        float mx = sc[0];
        for (int s = 1; s < 21; s++) mx = fmaxf(mx, sc[s]);
        float sum = 0.f;
        for (int s = 0; s < 21; s++) { float e = expf(sc[s] - mx); wts[s] = e; sum += e; }
        float inv = 1.f / sum;
        for (int s = 0; s < 21; s++) wts[s] *= inv;
    }
    __syncthreads();
    // pass 2: vectorized — 256 threads x 4 halfs
    __half* out = hcat16 + (size_t)b * 2048;
    {
        int q = tid;
        float a0, a1, a2, a3;
        {
            float2 hv = ((const float2*)hs16)[q];
            const __half2* h2 = (const __half2*)&hv;
            float2 x0 = __half22float2(h2[0]), x1 = __half22float2(h2[1]);
            float wv = wts[TIN];
            a0 = wv * x0.x; a1 = wv * x0.y; a2 = wv * x1.x; a3 = wv * x1.y;
        }
#pragma unroll
        for (int s = 0; s < TIN; s++) {
            float2 hv = ((const float2*)(allh16 + ((size_t)s * BB + b) * HH))[q];
            const __half2* h2 = (const __half2*)&hv;
            float2 x0 = __half22float2(h2[0]), x1 = __half22float2(h2[1]);
            float wv = wts[s];
            a0 += wv * x0.x; a1 += wv * x0.y; a2 += wv * x1.x; a3 += wv * x1.y;
        }
#pragma unroll
        for (int s = TIN + 1; s < 21; s++) {
            float2 hv = ((const float2*)(allhz16 + ((size_t)(s - TIN - 1) * BB + b) * HH))[q];
            const __half2* h2 = (const __half2*)&hv;
            float2 x0 = __half22float2(h2[0]), x1 = __half22float2(h2[1]);
            float wv = wts[s];
            a0 += wv * x0.x; a1 += wv * x0.y; a2 += wv * x1.x; a3 += wv * x1.y;
        }
        ((__half2*)out)[2 * q] = __floats2half2_rn(a0, a1);
        ((__half2*)out)[2 * q + 1] = __floats2half2_rn(a2, a3);
        ((float2*)(out + HH))[q] = ((const float2*)hs16)[q];
    }
}

// ================= small setup kernels =================
__global__ void prep_bias2_k(const float* wihA, const float* vecA, const float* b1A, const float* b2A, float* outA,
                             const float* wihB, const float* vecB, const float* b1B, const float* b2B, float* outB) {
    const float* wih = blockIdx.y ? wihB : wihA;
    const float* vec = blockIdx.y ? vecB : vecA;
    const float* b1  = blockIdx.y ? b1B  : b1A;
    const float* b2  = blockIdx.y ? b2B  : b2A;
    float* out       = blockIdx.y ? outB : outA;
    int wid = (blockIdx.x * blockDim.x + threadIdx.x) >> 5;
    int lane = threadIdx.x & 31;
    if (wid >= GG) return;
    const float* row = wih + (size_t)wid * DD;
    float s = 0.f;
    for (int d = lane; d < DD; d += 32) s += row[d] * vec[d];
#pragma unroll
    for (int off = 16; off; off >>= 1) s += __shfl_down_sync(0xffffffffu, s, off);
    if (lane == 0) out[wid] = b1[wid] + b2[wid] + s;
}

__global__ void f2h2_k(const float* __restrict__ s0, __half* __restrict__ d0,
                       const float* __restrict__ s1, __half* __restrict__ d1, int n) {
    int i = blockIdx.x * blockDim.x + threadIdx.x;
    const float* s = blockIdx.y ? s1 : s0;
    __half* d = blockIdx.y ? d1 : d0;
    if (i < n) d[i] = __float2half(s[i]);
}

__global__ void pack_wcat16_k(const float* __restrict__ whh, const float* __restrict__ weff) {
    size_t idx = (size_t)blockIdx.x * blockDim.x + threadIdx.x;
    if (idx >= (size_t)GG * 2048) return;
    int j = (int)(idx >> 11), m = (int)(idx & 2047);
    float v = (m < 1024) ? whh[(size_t)j * 1024 + m] : weff[(size_t)j * 1024 + (m - 1024)];
    d_Wcat16[idx] = __float2half(v);
}

__global__ void pose_fin_k(const float* __restrict__ pc, const float* __restrict__ pb,
                           float* __restrict__ out) {
    int idx = blockIdx.x * blockDim.x + threadIdx.x;
    if (idx >= BB * TOUT * PP) return;
    int pp = idx % PP;
    int bt = idx / PP;
    int t = bt % TOUT, b = bt / TOUT;
    out[idx] = pc[((size_t)t * BB + b) * 256 + pp] + pb[pp];
}

// ================= host orchestration =================
extern "C" void kernel_launch(void* const* d_in, const int* in_sizes, int n_in,
                              void* d_out, int out_size) {
    const float* x        = (const float*)d_in[0];
    const float* z        = (const float*)d_in[1];
    const float* wf       = (const float*)d_in[2];
    const float* bf       = (const float*)d_in[3];
    const float* enc_wih  = (const float*)d_in[4];
    const float* enc_whh  = (const float*)d_in[5];
    const float* enc_bih  = (const float*)d_in[6];
    const float* enc_bhh  = (const float*)d_in[7];
    const float* encp_wih = (const float*)d_in[8];
    const float* encp_whh = (const float*)d_in[9];
    const float* encp_bih = (const float*)d_in[10];
    const float* encp_bhh = (const float*)d_in[11];
    const float* dec_wih  = (const float*)d_in[12];
    const float* dec_whh  = (const float*)d_in[13];
    const float* dec_bih  = (const float*)d_in[14];
    const float* dec_bhh  = (const float*)d_in[15];
    const float* lin_w    = (const float*)d_in[16];
    const float* lin_b    = (const float*)d_in[17];
    const float* pose_w   = (const float*)d_in[18];
    const float* pose_b   = (const float*)d_in[19];
    float* out = (float*)d_out;

    void* pv;
    cudaGetSymbolAddress(&pv, d_WcombX);  float* WcombX  = (float*)pv;
    cudaGetSymbolAddress(&pv, d_WcombZ);  float* WcombZ  = (float*)pv;
    cudaGetSymbolAddress(&pv, d_bcombX);  float* bcombX  = (float*)pv;
    cudaGetSymbolAddress(&pv, d_bcombZ);  float* bcombZ  = (float*)pv;
    cudaGetSymbolAddress(&pv, d_WeffF);   float* WeffF   = (float*)pv;
    cudaGetSymbolAddress(&pv, d_Wcat16);  __half* Wcat16 = (__half*)pv;
    cudaGetSymbolAddress(&pv, d_whhX16);  __half* whhX16 = (__half*)pv;
    cudaGetSymbolAddress(&pv, d_whhZ16);  __half* whhZ16 = (__half*)pv;
    cudaGetSymbolAddress(&pv, d_bcat);    float* bcat    = (float*)pv;
    cudaGetSymbolAddress(&pv, d_ginX);    float* ginX    = (float*)pv;
    cudaGetSymbolAddress(&pv, d_ginZ);    float* ginZ    = (float*)pv;
    cudaGetSymbolAddress(&pv, d_allh16X); __half* allh16X = (__half*)pv;
    cudaGetSymbolAddress(&pv, d_allh16Z); __half* allh16Z = (__half*)pv;
    cudaGetSymbolAddress(&pv, d_cX);      float* cX      = (float*)pv;
    cudaGetSymbolAddress(&pv, d_cZ);      float* cZ      = (float*)pv;
    cudaGetSymbolAddress(&pv, d_decc);    float* decc    = (float*)pv;
    cudaGetSymbolAddress(&pv, d_gates);   float* gates   = (float*)pv;
    cudaGetSymbolAddress(&pv, d_hcat16);  __half* hcat16 = (__half*)pv;
    cudaGetSymbolAddress(&pv, d_dechs);   float* dechs   = (float*)pv;
    cudaGetSymbolAddress(&pv, d_dechs16); __half* dechs16 = (__half*)pv;
    cudaGetSymbolAddress(&pv, d_poseC);   float* poseC   = (float*)pv;

    cudaFuncSetAttribute(hgemm_k<A_PLAIN, B_KN, true, false>, cudaFuncAttributeMaxDynamicSharedMemorySize, SMEM_KN_BYTES);
    cudaFuncSetAttribute(hgemm_k<A_XG,    B_NK, false, true>, cudaFuncAttributeMaxDynamicSharedMemorySize, SMEM_NK_BYTES);
    cudaFuncSetAttribute(hgemm_k<A_PLAIN, B_KN, true, true>,  cudaFuncAttributeMaxDynamicSharedMemorySize, SMEM_KN_BYTES);
    cudaFuncSetAttribute(hgemm_k<A_PLAIN, B_NK, true, true>,  cudaFuncAttributeMaxDynamicSharedMemorySize, SMEM_NK_BYTES);
    cudaFuncSetAttribute(hgemm16_k, cudaFuncAttributeMaxDynamicSharedMemorySize, H_SMEM_BYTES);

    // ---- Wcomb = enc_wih @ wf (tf32, both encoders) ----
    {
        GP p0 = {enc_wih,  wf, WcombX, GG, PP, DD, DD, PP, 256};
        GP p1 = {encp_wih, wf, WcombZ, GG, PP, DD, DD, PP, 256};
        hgemm_k<A_PLAIN, B_KN, true, false><<<dim3(GG / 128, 1, 2), 256, SMEM_KN_BYTES>>>(p0, p1);
    }
    // ---- gin = x @ Wcomb^T (tf32, both encoders) ----
    {
        GP p0 = {x, WcombX, ginX, TIN * BB, GG, PP, PP, 256, GG};
        GP p1 = {z, WcombZ, ginZ, TIN * BB, GG, PP, PP, 256, GG};
        hgemm_k<A_XG, B_NK, false, true><<<dim3(TIN * BB / 128, GG / 128, 2), 256, SMEM_NK_BYTES>>>(p0, p1);
    }
    // ---- whh -> fp16 (both encoders, one launch) ----
    f2h2_k<<<dim3((GG * HH + 255) / 256, 2), 256>>>(enc_whh, whhX16, encp_whh, whhZ16, GG * HH);
    // ---- folded biases (both encoders, one launch) ----
    prep_bias2_k<<<dim3(512, 2), 256>>>(enc_wih, bf, enc_bih, enc_bhh, bcombX,
                                        encp_wih, bf, encp_bih, encp_bhh, bcombZ);

    // ---- encoder t=0 ----
    {
        CP pa = {ginX, nullptr, bcombX, nullptr, cX, nullptr, allh16X};
        CP pb = {ginZ, nullptr, bcombZ, nullptr, cZ, nullptr, allh16Z};
        lstm_cell_k<<<dim3(4096, 2), 256>>>(pa, pb, 1);
    }
    // ---- encoder recurrence (fp16 GEMM) ----
    for (int t = 1; t < TIN; t++) {
        GP16 p0 = {allh16X + (size_t)(t - 1) * BB * HH, whhX16, gates,                   BB, GG, HH, HH, HH, GG};
        GP16 p1 = {allh16Z + (size_t)(t - 1) * BB * HH, whhZ16, gates + (size_t)BB * GG, BB, GG, HH, HH, HH, GG};
        hgemm16_k<<<dim3(BB / 128, GG / 128, 2), 256, H_SMEM_BYTES>>>(p0, p1);
        CP pa = {gates,                   ginX + (size_t)t * BB * GG, bcombX, cX, cX, nullptr, allh16X + (size_t)t * BB * HH};
        CP pb = {gates + (size_t)BB * GG, ginZ + (size_t)t * BB * GG, bcombZ, cZ, cZ, nullptr, allh16Z + (size_t)t * BB * HH};
        lstm_cell_k<<<dim3(4096, 2), 256>>>(pa, pb, 0);
    }

    // ---- decoder setup ----
    {   // Weff = dec_wih @ lin_w (tf32, f32 out)
        GP p0 = {dec_wih, lin_w, WeffF, GG, HH, DD, DD, HH, HH};
        hgemm_k<A_PLAIN, B_KN, true, true><<<dim3(GG / 128, HH / 128, 1), 256, SMEM_KN_BYTES>>>(p0, p0);
    }
    pack_wcat16_k<<<(int)(((size_t)GG * 2048 + 255) / 256), 256>>>(dec_whh, WeffF);
    prep_bias2_k<<<dim3(512, 1), 256>>>(dec_wih, lin_b, dec_bih, dec_bhh, bcat,
                                        dec_wih, lin_b, dec_bih, dec_bhh, bcat);

    // ---- decoder: attention(0) standalone, then GEMM + fused(cell+next attention) ----
    attention_k<<<BB, 256>>>(allh16X, allh16Z,
                             allh16X + (size_t)(TIN - 1) * BB * HH, cX, hcat16);
    for (int t = 0; t < TOUT; t++) {
        GP16 p0 = {hcat16, Wcat16, gates, BB, GG, 2048, 2048, 2048, GG};
        hgemm16_k<<<dim3(BB / 128, GG / 128, 1), 256, H_SMEM_BYTES>>>(p0, p0);
        const float* cptr = (t == 0) ? cX : decc;
        if (t < TOUT - 1) {
            cellatt_k<<<BB, 256>>>(gates, bcat, cptr, decc,
                                   dechs + (size_t)t * BB * HH, dechs16 + (size_t)t * BB * HH,
                                   allh16X, allh16Z, hcat16);
        } else {
            CP pa = {gates, nullptr, bcat, cptr, decc,
                     dechs + (size_t)t * BB * HH, dechs16 + (size_t)t * BB * HH};
            lstm_cell_k<<<dim3(4096, 1), 256>>>(pa, pa, 0);
        }
    }

    // ---- output projection (tf32) + epilogue ----
    {
        GP p0 = {dechs, pose_w, poseC, TOUT * BB, PP, HH, HH, HH, 256};
        hgemm_k<A_PLAIN, B_NK, true, true><<<dim3(TOUT * BB / 128, 1, 1), 256, SMEM_NK_BYTES>>>(p0, p0);
        pose_fin_k<<<(BB * TOUT * PP + 255) / 256, 256>>>(poseC, pose_b, out);
    }
}